// round 6
// baseline (speedup 1.0000x reference)
#include <cuda_runtime.h>
#include <math.h>

constexpr int NV = 50000, NC = 210000, NE = 630000, NG = 32, ROUNDS = 16;
typedef unsigned long long ull;

// ----------------- device scratch -----------------
__device__ float g_vars   [NV*64];
__device__ float g_clauses[NC*64];
__device__ float g_qh     [NV*64];
__device__ float g_lits   [2*NV*64];
__device__ float g_sig    [NV*64];
__device__ float g_cl     [NC*64];
__device__ float g_ch     [NC*128];
__device__ float g_cd     [NC*128];
__device__ float g_uin    [NV*256];
__device__ float g_uh     [NV*128];
__device__ float g_uh2    [NV*128];
__device__ float g_vraw   [NV*64];
__device__ int   g_deg    [2*NV];
__device__ int   g_off    [2*NV+1];
__device__ int   g_cur    [2*NV];
__device__ int   g_pcl    [NE];
__device__ float g_dw     [2*NV];
__device__ float g_vdw    [NV];
__device__ int   g_gcnt   [2*NG];
__device__ float g_stat   [2*NG*64];
__device__ float g_mean   [NG*64];
__device__ float g_rsig   [NG*64];

__device__ __forceinline__ float lrelu(float x){ return x > 0.f ? x : 0.2f*x; }
__device__ __forceinline__ float sp(float x){ return fmaxf(x,0.f) + log1pf(expf(-fabsf(x))); }

// packed f32x2 helpers (sm_103a FFMA2 — only reachable via PTX)
__device__ __forceinline__ ull pk2(float x, float y){
  ull r; asm("mov.b64 %0, {%1, %2};" : "=l"(r) : "f"(x), "f"(y)); return r;
}
__device__ __forceinline__ void upk(ull v, float& x, float& y){
  asm("mov.b64 {%0, %1}, %2;" : "=f"(x), "=f"(y) : "l"(v));
}
__device__ __forceinline__ void ffma2(ull& d, ull a, ull b){
  asm("fma.rn.f32x2 %0, %1, %2, %3;" : "=l"(d) : "l"(a), "l"(b), "l"(d));
}

// ----------------- setup -----------------
__global__ void k_setup0(){
  int i = blockIdx.x*blockDim.x + threadIdx.x, s = gridDim.x*blockDim.x;
  for(int j=i;j<2*NV;j+=s) g_deg[j]=0;
  if(i<2*NG) g_gcnt[i]=0;
}
__global__ void k_count(const int* __restrict__ lit, const int* __restrict__ vg,
                        const int* __restrict__ cg){
  int i = blockIdx.x*blockDim.x + threadIdx.x, s = gridDim.x*blockDim.x;
  for(int j=i;j<NE;j+=s) atomicAdd(&g_deg[lit[j]],1);
  for(int j=i;j<NV;j+=s) atomicAdd(&g_gcnt[NG+vg[j]],1);
  for(int j=i;j<NC;j+=s) atomicAdd(&g_gcnt[cg[j]],1);
}
__global__ void k_scan(){
  __shared__ int sh[1024];
  __shared__ int carry;
  int tid = threadIdx.x;
  if(tid==0) carry=0;
  __syncthreads();
  for(int base=0; base<2*NV; base+=1024){
    int i = base + tid;
    int v = (i < 2*NV) ? g_deg[i] : 0;
    sh[tid] = v; __syncthreads();
    for(int d=1; d<1024; d<<=1){
      int t = (tid>=d) ? sh[tid-d] : 0;
      __syncthreads();
      sh[tid] += t;
      __syncthreads();
    }
    int excl = sh[tid] - v;
    int total = sh[1023];
    int c = carry;
    if(i < 2*NV){ g_off[i] = c + excl; g_cur[i] = c + excl; }
    __syncthreads();
    if(tid==0) carry = c + total;
    __syncthreads();
  }
  if(tid==0) g_off[2*NV] = carry;
}
__global__ void k_fill(const int* __restrict__ lit){
  int i = blockIdx.x*blockDim.x + threadIdx.x, s = gridDim.x*blockDim.x;
  for(int e=i;e<NE;e+=s){
    int l = lit[e];
    int p = atomicAdd(&g_cur[l],1);
    g_pcl[p] = e/3;
  }
}
__global__ void k_dw(){
  int i = blockIdx.x*blockDim.x + threadIdx.x;
  if(i<2*NV) g_dw[i] = rsqrtf(fmaxf((float)g_deg[i],1.f));
  if(i<NV)   g_vdw[i] = 4.f*rsqrtf(fmaxf((float)(g_deg[i]+g_deg[NV+i]),1.f));
}
__global__ void k_init1(){
  int i = blockIdx.x*blockDim.x + threadIdx.x, s = gridDim.x*blockDim.x;
  for(int j=i;j<NV*64;j+=s) g_vars[j]=1.f;
  for(int j=i;j<NC*64;j+=s) g_clauses[j]=1.f;
}
__global__ void k_zerof(float* __restrict__ p, int n){
  int i = blockIdx.x*blockDim.x + threadIdx.x;
  if(i<n) p[i]=0.f;
}

// ----------------- fused MLP layer (FFMA2 inner loop) -----------------
// C[M,N] = act(concat(A0[:,0:K0], s1*A1[:,0:K1]) @ W + b)
// ACT: 0=none, 1=leaky, 2=lits epilogue, 3=output head
template<int K0,int K1,int N,int ACT>
__global__ void __launch_bounds__(256) k_mlp(
    const float* __restrict__ A0, const float* __restrict__ A1, float s1,
    const float* __restrict__ W, const float* __restrict__ b,
    float* __restrict__ C, int M,
    const float* __restrict__ w2, const float* __restrict__ b2){
  constexpr int K = K0 + K1;
  constexpr int TN = N/16;   // cols per thread
  constexpr int TP = TN/2;   // packed col-pairs per thread
  __shared__ __align__(16) float sAT[64*64];
  __shared__ __align__(16) float sW[64*N];
  int tid = threadIdx.x;
  int tx = tid & 15, ty = tid >> 4;
  int base = blockIdx.x * 64;
  int c0 = tx*TN, r0 = ty*4;
  ull acc[4][TP];
  #pragma unroll
  for(int j=0;j<TP;j++){
    ull bv = pk2(b[c0+2*j], b[c0+2*j+1]);
    #pragma unroll
    for(int r=0;r<4;r++) acc[r][j] = bv;
  }
  for(int k0=0;k0<K;k0+=64){
    int kc = (K-k0 < 64) ? (K-k0) : 64;
    __syncthreads();
    {
      const float4* Wsrc = (const float4*)(W + (size_t)k0*N);
      float4* Wdst = (float4*)sW;
      for(int i=tid;i<kc*N/4;i+=256) Wdst[i] = Wsrc[i];
    }
    {
      int nq = kc >> 2;
      for(int i=tid;i<64*nq;i+=256){
        int r = i & 63, kq = i >> 6;
        int col = k0 + kq*4;
        int row = base + r;
        float4 v = make_float4(0.f,0.f,0.f,0.f);
        if(row < M){
          if(col < K0) v = *(const float4*)&A0[(size_t)row*K0 + col];
          else {
            v = *(const float4*)&A1[(size_t)row*K1 + (col-K0)];
            v.x*=s1; v.y*=s1; v.z*=s1; v.w*=s1;
          }
        }
        int kk = kq*4;
        sAT[(kk+0)*64+r]=v.x; sAT[(kk+1)*64+r]=v.y;
        sAT[(kk+2)*64+r]=v.z; sAT[(kk+3)*64+r]=v.w;
      }
    }
    __syncthreads();
    const ull* sWp = (const ull*)sW;
    #pragma unroll 4
    for(int k=0;k<kc;k++){
      float4 a = *(const float4*)&sAT[k*64 + r0];
      ull w2r[TP];
      #pragma unroll
      for(int j0=0;j0<TP;j0++) w2r[j0] = sWp[(k*N + c0)/2 + j0];
      ull a2[4] = {pk2(a.x,a.x), pk2(a.y,a.y), pk2(a.z,a.z), pk2(a.w,a.w)};
      #pragma unroll
      for(int r=0;r<4;r++)
        #pragma unroll
        for(int j=0;j<TP;j++) ffma2(acc[r][j], a2[r], w2r[j]);
    }
  }
  if(ACT==0 || ACT==1){
    #pragma unroll
    for(int r=0;r<4;r++){
      int row = base + r0 + r;
      if(row < M){
        #pragma unroll
        for(int j0=0;j0<TP;j0+=2){
          float4 o;
          upk(acc[r][j0],   o.x, o.y);
          upk(acc[r][j0+1], o.z, o.w);
          if(ACT==1){ o.x=lrelu(o.x); o.y=lrelu(o.y); o.z=lrelu(o.z); o.w=lrelu(o.w); }
          *(float4*)&C[(size_t)row*N + c0 + j0*2] = o;
        }
      }
    }
  } else if(ACT==2){
    #pragma unroll
    for(int r=0;r<4;r++){
      int row = base + r0 + r;
      if(row < M){
        float q[4];
        upk(acc[r][0], q[0], q[1]);
        upk(acc[r][1], q[2], q[3]);
        float4 lp, ln, sg;
        lp.x = sp( q[0]); lp.y = sp( q[1]); lp.z = sp( q[2]); lp.w = sp( q[3]);
        ln.x = sp(-q[0]); ln.y = sp(-q[1]); ln.z = sp(-q[2]); ln.w = sp(-q[3]);
        sg.x = 1.f/(1.f+expf(-q[0])); sg.y = 1.f/(1.f+expf(-q[1]));
        sg.z = 1.f/(1.f+expf(-q[2])); sg.w = 1.f/(1.f+expf(-q[3]));
        *(float4*)&g_lits[(size_t)row*64 + c0]      = lp;
        *(float4*)&g_lits[(size_t)(NV+row)*64 + c0] = ln;
        *(float4*)&g_sig [(size_t)row*64 + c0]      = sg;
      }
    }
  } else { // ACT==3
    float p[4];
    #pragma unroll
    for(int r=0;r<4;r++){
      float v[4];
      upk(acc[r][0], v[0], v[1]);
      upk(acc[r][1], v[2], v[3]);
      float s = 0.f;
      #pragma unroll
      for(int j=0;j<TN;j++) s += lrelu(v[j]) * w2[c0+j];
      p[r] = s;
    }
    #pragma unroll
    for(int r=0;r<4;r++){
      #pragma unroll
      for(int o=8;o>0;o>>=1) p[r] += __shfl_down_sync(0xffffffffu, p[r], o, 16);
    }
    if(tx==0){
      float bb = b2[0];
      #pragma unroll
      for(int r=0;r<4;r++){
        int row = base + r0 + r;
        if(row < M){
          float logit = p[r] + bb;
          C[row]      = 1.f/(1.f+expf(-logit));
          C[NC + row] = sp(logit);
        }
      }
    }
  }
}

// ----------------- per-round graph kernels -----------------
__global__ void k_cl(const int* __restrict__ lit){
  int idx = blockIdx.x*blockDim.x + threadIdx.x;
  if(idx >= NC*16) return;
  int c = idx >> 4, q = (idx & 15) * 4;
  int e = 3*c;
  int l0 = lit[e], l1 = lit[e+1], l2 = lit[e+2];
  float4 A = *(const float4*)&g_lits[(size_t)l0*64 + q];
  float4 B = *(const float4*)&g_lits[(size_t)l1*64 + q];
  float4 C = *(const float4*)&g_lits[(size_t)l2*64 + q];
  float4 o;
  o.x = expf(-(A.x+B.x+C.x)); o.y = expf(-(A.y+B.y+C.y));
  o.z = expf(-(A.z+B.z+C.z)); o.w = expf(-(A.w+B.w+C.w));
  *(float4*)&g_cl[(size_t)c*64 + q] = o;
}

__global__ void __launch_bounds__(256) k_uin(){
  int tid = threadIdx.x;
  int f = tid & 63;
  int v = blockIdx.x*4 + (tid >> 6);
  if(v >= NV) return;
  int p0 = g_off[v],    p1 = g_off[v+1];
  int n0 = g_off[NV+v], n1 = g_off[NV+v+1];
  float scl=0.f, scd=0.f, ncl=0.f, ncd=0.f;
  for(int e=p0;e<p1;e++){
    int c = g_pcl[e];
    scl += g_cl[(size_t)c*64 + f];
    scd += g_cd[(size_t)c*128 + f];
  }
  for(int e=n0;e<n1;e++){
    int c = g_pcl[e];
    ncl += g_cl[(size_t)c*64 + f];
    ncd += g_cd[(size_t)c*128 + f];
  }
  float sg = g_sig[(size_t)v*64 + f];
  float gr = (-sg*scl + (1.f-sg)*ncl) * g_vdw[v];
  size_t o = (size_t)v*256;
  g_uin[o + f]       = gr;
  g_uin[o + 64 + f]  = g_vars[(size_t)v*64 + f];
  g_uin[o + 128 + f] = scd * g_dw[v];
  g_uin[o + 192 + f] = ncd * g_dw[NV+v];
}

// ----------------- pair-norm -----------------
__global__ void k_stats(const float* __restrict__ src, int S, int off,
                        const int* __restrict__ gid, int n){
  __shared__ float s1[256], s2[256];
  int tid = threadIdx.x;
  int f = tid & 63, lane = tid >> 6;
  int row0 = blockIdx.x * 64;
  int rend = min(row0 + 64, n);
  int g0 = gid[row0], g1 = gid[rend-1];
  if(g0 == g1){
    float s = 0.f, q = 0.f;
    for(int r = row0 + lane; r < rend; r += 4){
      float x = src[(size_t)r*S + off + f];
      s += x; q += x*x;
    }
    s1[tid] = s; s2[tid] = q;
    __syncthreads();
    if(lane == 0){
      s = s1[f] + s1[64+f] + s1[128+f] + s1[192+f];
      q = s2[f] + s2[64+f] + s2[128+f] + s2[192+f];
      atomicAdd(&g_stat[g0*64 + f], s);
      atomicAdd(&g_stat[NG*64 + g0*64 + f], q);
    }
  } else {
    for(int r = row0 + lane; r < rend; r += 4){
      float x = src[(size_t)r*S + off + f];
      int g = gid[r];
      atomicAdd(&g_stat[g*64 + f], x);
      atomicAdd(&g_stat[NG*64 + g*64 + f], x*x);
    }
  }
}
__global__ void k_fin(int cntoff){
  int i = blockIdx.x*blockDim.x + threadIdx.x;
  if(i >= NG*64) return;
  int g = i >> 6;
  float inv = 1.f / fmaxf((float)g_gcnt[cntoff + g], 1.f);
  float m = g_stat[i] * inv;
  float var = g_stat[NG*64 + i] * inv - m*m;
  g_mean[i] = m;
  g_rsig[i] = rsqrtf(fmaxf(var, 0.f) + 1e-6f);
}
__global__ void k_apply(const float* __restrict__ src, int S, int off,
                        float* __restrict__ target, const int* __restrict__ gid, int n){
  int i = blockIdx.x*blockDim.x + threadIdx.x;
  if(i >= n*64) return;
  int r = i >> 6, f = i & 63;
  int g = gid[r];
  float x = src[(size_t)r*S + off + f];
  float y = (x - g_mean[g*64+f]) * g_rsig[g*64+f] * 0.25f;
  target[i] = y + 0.1f * target[i];
}

// ----------------- host -----------------
static float* fsym(const void* s){ void* p=nullptr; cudaGetSymbolAddress(&p, s); return (float*)p; }

extern "C" void kernel_launch(void* const* d_in, const int* in_sizes, int n_in,
                              void* d_out, int out_size){
  const int*   lit   = (const int*)d_in[0];
  const int*   vg    = (const int*)d_in[2];
  const int*   cg    = (const int*)d_in[3];
  const float* noise = (const float*)d_in[4];
  const float *qW0=(const float*)d_in[5],  *qb0=(const float*)d_in[6];
  const float *qW1=(const float*)d_in[7],  *qb1=(const float*)d_in[8];
  const float *cW0=(const float*)d_in[9],  *cb0=(const float*)d_in[10];
  const float *cW1=(const float*)d_in[11], *cb1=(const float*)d_in[12];
  const float *uW0=(const float*)d_in[13], *ub0=(const float*)d_in[14];
  const float *uW1=(const float*)d_in[15], *ub1=(const float*)d_in[16];
  const float *uW2=(const float*)d_in[17], *ub2=(const float*)d_in[18];
  const float *oW0=(const float*)d_in[19], *ob0=(const float*)d_in[20];
  const float *oW1=(const float*)d_in[21], *ob1=(const float*)d_in[22];
  float* out = (float*)d_out;

  float *p_qh   = fsym(g_qh);
  float *p_ch   = fsym(g_ch),  *p_cd   = fsym(g_cd),  *p_cl = fsym(g_cl);
  float *p_uin  = fsym(g_uin), *p_uh   = fsym(g_uh),  *p_uh2 = fsym(g_uh2);
  float *p_vraw = fsym(g_vraw),*p_vars = fsym(g_vars);
  float *p_claus= fsym(g_clauses);
  float *p_stat = fsym(g_stat);

  const int T = 256;
  auto B = [](long n){ return (int)((n + 255) / 256); };
  int gbV = (NV + 63) / 64, gbC = (NC + 63) / 64;

  k_setup0<<<256, T>>>();
  k_count<<<1024, T>>>(lit, vg, cg);
  k_scan<<<1, 1024>>>();
  k_fill<<<1024, T>>>(lit);
  k_dw<<<B(2L*NV), T>>>();
  k_init1<<<4096, T>>>();

  for(int t = 0; t < ROUNDS; t++){
    const float* nz = noise + (size_t)t * NV * 4;
    k_mlp<64,4,64,1><<<gbV, T>>>(p_vars, nz, 1.f, qW0, qb0, p_qh, NV, nullptr, nullptr);
    k_mlp<64,0,64,2><<<gbV, T>>>(p_qh, nullptr, 0.f, qW1, qb1, nullptr, NV, nullptr, nullptr);
    k_cl<<<B((long)NC*16), T>>>(lit);

    k_mlp<64,64,128,1><<<gbC, T>>>(p_claus, p_cl, 4.f, cW0, cb0, p_ch, NC, nullptr, nullptr);
    k_mlp<128,0,128,0><<<gbC, T>>>(p_ch, nullptr, 0.f, cW1, cb1, p_cd, NC, nullptr, nullptr);

    k_zerof<<<B(2L*NG*64), T>>>(p_stat, 2*NG*64);
    k_stats<<<gbC, T>>>(p_cd, 128, 64, cg, NC);
    k_fin<<<8, T>>>(0);
    k_apply<<<B((long)NC*64), T>>>(p_cd, 128, 64, p_claus, cg, NC);

    k_uin<<<(NV+3)/4, T>>>();

    k_mlp<256,0,128,1><<<gbV, T>>>(p_uin, nullptr, 0.f, uW0, ub0, p_uh, NV, nullptr, nullptr);
    k_mlp<128,0,128,1><<<gbV, T>>>(p_uh,  nullptr, 0.f, uW1, ub1, p_uh2, NV, nullptr, nullptr);
    k_mlp<128,0,64,0 ><<<gbV, T>>>(p_uh2, nullptr, 0.f, uW2, ub2, p_vraw, NV, nullptr, nullptr);

    k_zerof<<<B(2L*NG*64), T>>>(p_stat, 2*NG*64);
    k_stats<<<gbV, T>>>(p_vraw, 64, 0, vg, NV);
    k_fin<<<8, T>>>(NG);
    k_apply<<<B((long)NV*64), T>>>(p_vraw, 64, 0, p_vars, vg, NV);
  }

  k_mlp<64,0,64,3><<<gbC, T>>>(p_claus, nullptr, 0.f, oW0, ob0, out, NC, oW1, ob1);

  (void)in_sizes; (void)n_in; (void)out_size;
}

// round 7
// speedup vs baseline: 1.7993x; 1.7993x over previous
#include <cuda_runtime.h>
#include <math.h>
#include <stdint.h>

constexpr int NV = 50000, NC = 210000, NE = 630000, NG = 32, ROUNDS = 16;

// ----------------- device scratch -----------------
__device__ float g_vars   [NV*64];
__device__ float g_clauses[NC*64];
__device__ float g_qh     [NV*64];
__device__ float g_lits   [2*NV*64];
__device__ float g_sig    [NV*64];
__device__ float g_cl     [NC*64];
__device__ float g_ch     [NC*128];
__device__ float g_cd     [NC*128];
__device__ float g_uin    [NV*256];
__device__ float g_uh     [NV*128];
__device__ float g_uh2    [NV*128];
__device__ float g_vraw   [NV*64];
__device__ int   g_deg    [2*NV];
__device__ int   g_off    [2*NV+1];
__device__ int   g_cur    [2*NV];
__device__ int   g_pcl    [NE];
__device__ float g_dw     [2*NV];
__device__ float g_vdw    [NV];
__device__ int   g_gcnt   [2*NG];
__device__ float g_stat   [2*NG*64];
__device__ float g_mean   [NG*64];
__device__ float g_rsig   [NG*64];

__device__ __forceinline__ float lrelu(float x){ return x > 0.f ? x : 0.2f*x; }
__device__ __forceinline__ float sp(float x){ return fmaxf(x,0.f) + log1pf(expf(-fabsf(x))); }
__device__ __forceinline__ uint32_t to_tf32(float x){
  uint32_t r; asm("cvt.rna.tf32.f32 %0, %1;" : "=r"(r) : "f"(x)); return r;
}
__device__ __forceinline__ void mma8(float* c, const uint32_t* a, const uint32_t* b){
  asm("mma.sync.aligned.m16n8k8.row.col.f32.tf32.tf32.f32 "
      "{%0,%1,%2,%3},{%4,%5,%6,%7},{%8,%9},{%0,%1,%2,%3};"
      : "+f"(c[0]),"+f"(c[1]),"+f"(c[2]),"+f"(c[3])
      : "r"(a[0]),"r"(a[1]),"r"(a[2]),"r"(a[3]), "r"(b[0]),"r"(b[1]));
}

// ----------------- setup -----------------
__global__ void k_setup0(){
  int i = blockIdx.x*blockDim.x + threadIdx.x, s = gridDim.x*blockDim.x;
  for(int j=i;j<2*NV;j+=s) g_deg[j]=0;
  if(i<2*NG) g_gcnt[i]=0;
}
__global__ void k_count(const int* __restrict__ lit, const int* __restrict__ vg,
                        const int* __restrict__ cg){
  int i = blockIdx.x*blockDim.x + threadIdx.x, s = gridDim.x*blockDim.x;
  for(int j=i;j<NE;j+=s) atomicAdd(&g_deg[lit[j]],1);
  for(int j=i;j<NV;j+=s) atomicAdd(&g_gcnt[NG+vg[j]],1);
  for(int j=i;j<NC;j+=s) atomicAdd(&g_gcnt[cg[j]],1);
}
__global__ void k_scan(){
  __shared__ int sh[1024];
  __shared__ int carry;
  int tid = threadIdx.x;
  if(tid==0) carry=0;
  __syncthreads();
  for(int base=0; base<2*NV; base+=1024){
    int i = base + tid;
    int v = (i < 2*NV) ? g_deg[i] : 0;
    sh[tid] = v; __syncthreads();
    for(int d=1; d<1024; d<<=1){
      int t = (tid>=d) ? sh[tid-d] : 0;
      __syncthreads();
      sh[tid] += t;
      __syncthreads();
    }
    int excl = sh[tid] - v;
    int total = sh[1023];
    int c = carry;
    if(i < 2*NV){ g_off[i] = c + excl; g_cur[i] = c + excl; }
    __syncthreads();
    if(tid==0) carry = c + total;
    __syncthreads();
  }
  if(tid==0) g_off[2*NV] = carry;
}
__global__ void k_fill(const int* __restrict__ lit){
  int i = blockIdx.x*blockDim.x + threadIdx.x, s = gridDim.x*blockDim.x;
  for(int e=i;e<NE;e+=s){
    int l = lit[e];
    int p = atomicAdd(&g_cur[l],1);
    g_pcl[p] = e/3;
  }
}
__global__ void k_dw(){
  int i = blockIdx.x*blockDim.x + threadIdx.x;
  if(i<2*NV) g_dw[i] = rsqrtf(fmaxf((float)g_deg[i],1.f));
  if(i<NV)   g_vdw[i] = 4.f*rsqrtf(fmaxf((float)(g_deg[i]+g_deg[NV+i]),1.f));
}
__global__ void k_init1(){
  int i = blockIdx.x*blockDim.x + threadIdx.x, s = gridDim.x*blockDim.x;
  for(int j=i;j<NV*64;j+=s) g_vars[j]=1.f;
  for(int j=i;j<NC*64;j+=s) g_clauses[j]=1.f;
}
__global__ void k_zerof(float* __restrict__ p, int n){
  int i = blockIdx.x*blockDim.x + threadIdx.x;
  if(i<n) p[i]=0.f;
}

// ----------------- tensor-core MLP layer (tf32 mma.sync) -----------------
// C[M,N] = act(concat(A0[:,0:K0], s1*A1[:,0:K1]) @ W + b)
// ACT: 0=none, 1=leaky, 2=lits epilogue (g_lits/g_sig), 3=output head
// Tile: 128 rows x N cols per block; 8 warps, each owns 16 rows.
template<int K0,int K1,int N,int ACT>
__global__ void __launch_bounds__(256) k_mma(
    const float* __restrict__ A0, const float* __restrict__ A1, float s1,
    const float* __restrict__ W, const float* __restrict__ b,
    float* __restrict__ C, int M,
    const float* __restrict__ w2, const float* __restrict__ b2){
  constexpr int K  = K0 + K1;
  constexpr int KC = 32;          // k-chunk
  constexpr int KP = KC + 4;      // sA pitch (pad: conflict-free frag loads)
  constexpr int NP = N + 4;       // sW pitch
  constexpr int NT = N / 8;       // n-tiles of 8
  constexpr int NCHUNK = (K + KC - 1) / KC;
  __shared__ uint32_t sA[128*KP];
  __shared__ uint32_t sW[KC*NP];
  int tid = threadIdx.x;
  int w = tid >> 5, lane = tid & 31;
  int g = lane >> 2, tg = lane & 3;
  int base = blockIdx.x * 128;
  float acc[NT][4];
  #pragma unroll
  for(int j=0;j<NT;j++){
    int col = j*8 + 2*tg;
    float b0v = b[col], b1v = b[col+1];
    acc[j][0]=b0v; acc[j][1]=b1v; acc[j][2]=b0v; acc[j][3]=b1v;
  }
  for(int ch=0; ch<NCHUNK; ch++){
    int k0 = ch*KC;
    int kc = K - k0; if(kc > KC) kc = KC;
    __syncthreads();
    // fill W chunk [kc x N] (zero-pad to KC)
    for(int i=tid; i<KC*N; i+=256){
      int kk = i / N, n = i % N;
      float v = (kk < kc) ? W[(size_t)(k0+kk)*N + n] : 0.f;
      sW[kk*NP + n] = to_tf32(v);
    }
    // fill A chunk [128 x kc] (zero-pad to KC)
    for(int i=tid; i<128*KC; i+=256){
      int r = i >> 5, kk = i & (KC-1);
      int row = base + r, col = k0 + kk;
      float v = 0.f;
      if(row < M && kk < kc){
        v = (col < K0) ? A0[(size_t)row*K0 + col]
                       : s1 * A1[(size_t)row*K1 + (col - K0)];
      }
      sA[r*KP + kk] = to_tf32(v);
    }
    __syncthreads();
    int r0 = w*16;
    #pragma unroll
    for(int s=0;s<KC/8;s++){
      uint32_t a[4];
      int ks = s*8;
      a[0] = sA[(r0 + g    )*KP + ks + tg];
      a[1] = sA[(r0 + g + 8)*KP + ks + tg];
      a[2] = sA[(r0 + g    )*KP + ks + tg + 4];
      a[3] = sA[(r0 + g + 8)*KP + ks + tg + 4];
      #pragma unroll
      for(int j=0;j<NT;j++){
        uint32_t bb[2];
        bb[0] = sW[(ks + tg    )*NP + j*8 + g];
        bb[1] = sW[(ks + tg + 4)*NP + j*8 + g];
        mma8(acc[j], a, bb);
      }
    }
  }
  // epilogues
  int row0 = base + w*16 + g;
  int row1 = row0 + 8;
  if(ACT==0 || ACT==1){
    #pragma unroll
    for(int j=0;j<NT;j++){
      int col = j*8 + 2*tg;
      float2 o0, o1;
      o0.x = (ACT==1)? lrelu(acc[j][0]) : acc[j][0];
      o0.y = (ACT==1)? lrelu(acc[j][1]) : acc[j][1];
      o1.x = (ACT==1)? lrelu(acc[j][2]) : acc[j][2];
      o1.y = (ACT==1)? lrelu(acc[j][3]) : acc[j][3];
      if(row0 < M) *(float2*)&C[(size_t)row0*N + col] = o0;
      if(row1 < M) *(float2*)&C[(size_t)row1*N + col] = o1;
    }
  } else if(ACT==2){
    #pragma unroll
    for(int j=0;j<NT;j++){
      int col = j*8 + 2*tg;
      #pragma unroll
      for(int h=0;h<2;h++){
        int row = h ? row1 : row0;
        if(row < M){
          float qa = acc[j][2*h], qb = acc[j][2*h+1];
          float2 lp = make_float2(sp(qa), sp(qb));
          float2 ln = make_float2(sp(-qa), sp(-qb));
          float2 sg = make_float2(1.f/(1.f+expf(-qa)), 1.f/(1.f+expf(-qb)));
          *(float2*)&g_lits[(size_t)row*64 + col]      = lp;
          *(float2*)&g_lits[(size_t)(NV+row)*64 + col] = ln;
          *(float2*)&g_sig [(size_t)row*64 + col]      = sg;
        }
      }
    }
  } else { // ACT==3: head — dot(lrelu(acc), w2) per row + sigmoid/softplus
    float p0 = 0.f, p1 = 0.f;
    #pragma unroll
    for(int j=0;j<NT;j++){
      int col = j*8 + 2*tg;
      float wa = w2[col], wb = w2[col+1];
      p0 += lrelu(acc[j][0])*wa + lrelu(acc[j][1])*wb;
      p1 += lrelu(acc[j][2])*wa + lrelu(acc[j][3])*wb;
    }
    #pragma unroll
    for(int o=2;o>0;o>>=1){
      p0 += __shfl_down_sync(0xffffffffu, p0, o, 4);
      p1 += __shfl_down_sync(0xffffffffu, p1, o, 4);
    }
    if(tg == 0){
      float bb = b2[0];
      if(row0 < M){
        float lg = p0 + bb;
        C[row0] = 1.f/(1.f+expf(-lg)); C[NC + row0] = sp(lg);
      }
      if(row1 < M){
        float lg = p1 + bb;
        C[row1] = 1.f/(1.f+expf(-lg)); C[NC + row1] = sp(lg);
      }
    }
  }
}

// ----------------- per-round graph kernels -----------------
__global__ void k_cl(const int* __restrict__ lit){
  int idx = blockIdx.x*blockDim.x + threadIdx.x;
  if(idx >= NC*16) return;
  int c = idx >> 4, q = (idx & 15) * 4;
  int e = 3*c;
  int l0 = lit[e], l1 = lit[e+1], l2 = lit[e+2];
  float4 A = *(const float4*)&g_lits[(size_t)l0*64 + q];
  float4 B = *(const float4*)&g_lits[(size_t)l1*64 + q];
  float4 C = *(const float4*)&g_lits[(size_t)l2*64 + q];
  float4 o;
  o.x = expf(-(A.x+B.x+C.x)); o.y = expf(-(A.y+B.y+C.y));
  o.z = expf(-(A.z+B.z+C.z)); o.w = expf(-(A.w+B.w+C.w));
  *(float4*)&g_cl[(size_t)c*64 + q] = o;
}

__global__ void __launch_bounds__(256) k_uin(){
  int tid = threadIdx.x;
  int f = tid & 63;
  int v = blockIdx.x*4 + (tid >> 6);
  if(v >= NV) return;
  int p0 = g_off[v],    p1 = g_off[v+1];
  int n0 = g_off[NV+v], n1 = g_off[NV+v+1];
  float scl=0.f, scd=0.f, ncl=0.f, ncd=0.f;
  for(int e=p0;e<p1;e++){
    int c = g_pcl[e];
    scl += g_cl[(size_t)c*64 + f];
    scd += g_cd[(size_t)c*128 + f];
  }
  for(int e=n0;e<n1;e++){
    int c = g_pcl[e];
    ncl += g_cl[(size_t)c*64 + f];
    ncd += g_cd[(size_t)c*128 + f];
  }
  float sg = g_sig[(size_t)v*64 + f];
  float gr = (-sg*scl + (1.f-sg)*ncl) * g_vdw[v];
  size_t o = (size_t)v*256;
  g_uin[o + f]       = gr;
  g_uin[o + 64 + f]  = g_vars[(size_t)v*64 + f];
  g_uin[o + 128 + f] = scd * g_dw[v];
  g_uin[o + 192 + f] = ncd * g_dw[NV+v];
}

// ----------------- pair-norm -----------------
__global__ void k_stats(const float* __restrict__ src, int S, int off,
                        const int* __restrict__ gid, int n){
  __shared__ float s1[256], s2[256];
  int tid = threadIdx.x;
  int f = tid & 63, lane = tid >> 6;
  int row0 = blockIdx.x * 64;
  int rend = min(row0 + 64, n);
  int g0 = gid[row0], g1 = gid[rend-1];
  if(g0 == g1){
    float s = 0.f, q = 0.f;
    for(int r = row0 + lane; r < rend; r += 4){
      float x = src[(size_t)r*S + off + f];
      s += x; q += x*x;
    }
    s1[tid] = s; s2[tid] = q;
    __syncthreads();
    if(lane == 0){
      s = s1[f] + s1[64+f] + s1[128+f] + s1[192+f];
      q = s2[f] + s2[64+f] + s2[128+f] + s2[192+f];
      atomicAdd(&g_stat[g0*64 + f], s);
      atomicAdd(&g_stat[NG*64 + g0*64 + f], q);
    }
  } else {
    for(int r = row0 + lane; r < rend; r += 4){
      float x = src[(size_t)r*S + off + f];
      int g = gid[r];
      atomicAdd(&g_stat[g*64 + f], x);
      atomicAdd(&g_stat[NG*64 + g*64 + f], x*x);
    }
  }
}
__global__ void k_fin(int cntoff){
  int i = blockIdx.x*blockDim.x + threadIdx.x;
  if(i >= NG*64) return;
  int g = i >> 6;
  float inv = 1.f / fmaxf((float)g_gcnt[cntoff + g], 1.f);
  float m = g_stat[i] * inv;
  float var = g_stat[NG*64 + i] * inv - m*m;
  g_mean[i] = m;
  g_rsig[i] = rsqrtf(fmaxf(var, 0.f) + 1e-6f);
}
__global__ void k_apply(const float* __restrict__ src, int S, int off,
                        float* __restrict__ target, const int* __restrict__ gid, int n){
  int i = blockIdx.x*blockDim.x + threadIdx.x;
  if(i >= n*64) return;
  int r = i >> 6, f = i & 63;
  int g = gid[r];
  float x = src[(size_t)r*S + off + f];
  float y = (x - g_mean[g*64+f]) * g_rsig[g*64+f] * 0.25f;
  target[i] = y + 0.1f * target[i];
}

// ----------------- host -----------------
static float* fsym(const void* s){ void* p=nullptr; cudaGetSymbolAddress(&p, s); return (float*)p; }

extern "C" void kernel_launch(void* const* d_in, const int* in_sizes, int n_in,
                              void* d_out, int out_size){
  const int*   lit   = (const int*)d_in[0];
  const int*   vg    = (const int*)d_in[2];
  const int*   cg    = (const int*)d_in[3];
  const float* noise = (const float*)d_in[4];
  const float *qW0=(const float*)d_in[5],  *qb0=(const float*)d_in[6];
  const float *qW1=(const float*)d_in[7],  *qb1=(const float*)d_in[8];
  const float *cW0=(const float*)d_in[9],  *cb0=(const float*)d_in[10];
  const float *cW1=(const float*)d_in[11], *cb1=(const float*)d_in[12];
  const float *uW0=(const float*)d_in[13], *ub0=(const float*)d_in[14];
  const float *uW1=(const float*)d_in[15], *ub1=(const float*)d_in[16];
  const float *uW2=(const float*)d_in[17], *ub2=(const float*)d_in[18];
  const float *oW0=(const float*)d_in[19], *ob0=(const float*)d_in[20];
  const float *oW1=(const float*)d_in[21], *ob1=(const float*)d_in[22];
  float* out = (float*)d_out;

  float *p_qh   = fsym(g_qh);
  float *p_ch   = fsym(g_ch),  *p_cd   = fsym(g_cd),  *p_cl = fsym(g_cl);
  float *p_uin  = fsym(g_uin), *p_uh   = fsym(g_uh),  *p_uh2 = fsym(g_uh2);
  float *p_vraw = fsym(g_vraw),*p_vars = fsym(g_vars);
  float *p_claus= fsym(g_clauses);
  float *p_stat = fsym(g_stat);

  const int T = 256;
  auto B = [](long n){ return (int)((n + 255) / 256); };
  int mbV = (NV + 127) / 128, mbC = (NC + 127) / 128;
  int gbV = (NV + 63) / 64,   gbC = (NC + 63) / 64;

  k_setup0<<<256, T>>>();
  k_count<<<1024, T>>>(lit, vg, cg);
  k_scan<<<1, 1024>>>();
  k_fill<<<1024, T>>>(lit);
  k_dw<<<B(2L*NV), T>>>();
  k_init1<<<4096, T>>>();

  for(int t = 0; t < ROUNDS; t++){
    const float* nz = noise + (size_t)t * NV * 4;
    k_mma<64,4,64,1><<<mbV, T>>>(p_vars, nz, 1.f, qW0, qb0, p_qh, NV, nullptr, nullptr);
    k_mma<64,0,64,2><<<mbV, T>>>(p_qh, nullptr, 0.f, qW1, qb1, nullptr, NV, nullptr, nullptr);
    k_cl<<<B((long)NC*16), T>>>(lit);

    k_mma<64,64,128,1><<<mbC, T>>>(p_claus, p_cl, 4.f, cW0, cb0, p_ch, NC, nullptr, nullptr);
    k_mma<128,0,128,0><<<mbC, T>>>(p_ch, nullptr, 0.f, cW1, cb1, p_cd, NC, nullptr, nullptr);

    k_zerof<<<B(2L*NG*64), T>>>(p_stat, 2*NG*64);
    k_stats<<<gbC, T>>>(p_cd, 128, 64, cg, NC);
    k_fin<<<8, T>>>(0);
    k_apply<<<B((long)NC*64), T>>>(p_cd, 128, 64, p_claus, cg, NC);

    k_uin<<<(NV+3)/4, T>>>();

    k_mma<256,0,128,1><<<mbV, T>>>(p_uin, nullptr, 0.f, uW0, ub0, p_uh, NV, nullptr, nullptr);
    k_mma<128,0,128,1><<<mbV, T>>>(p_uh,  nullptr, 0.f, uW1, ub1, p_uh2, NV, nullptr, nullptr);
    k_mma<128,0,64,0 ><<<mbV, T>>>(p_uh2, nullptr, 0.f, uW2, ub2, p_vraw, NV, nullptr, nullptr);

    k_zerof<<<B(2L*NG*64), T>>>(p_stat, 2*NG*64);
    k_stats<<<gbV, T>>>(p_vraw, 64, 0, vg, NV);
    k_fin<<<8, T>>>(NG);
    k_apply<<<B((long)NV*64), T>>>(p_vraw, 64, 0, p_vars, vg, NV);
  }

  k_mma<64,0,64,3><<<mbC, T>>>(p_claus, nullptr, 0.f, oW0, ob0, out, NC, oW1, ob1);

  (void)in_sizes; (void)n_in; (void)out_size;
}

// round 8
// speedup vs baseline: 2.5481x; 1.4162x over previous
#include <cuda_runtime.h>
#include <math.h>
#include <stdint.h>

constexpr int NV = 50000, NC = 210000, NE = 630000, NG = 32, ROUNDS = 16;

// ----------------- device scratch -----------------
__device__ float g_vars   [NV*64];
__device__ float g_clauses[NC*64];
__device__ float g_qh     [NV*64];
__device__ float g_lits   [2*NV*64];
__device__ float g_sig    [NV*64];
__device__ float g_cl     [NC*64];
__device__ float g_ch     [NC*128];
__device__ float g_cd     [NC*128];
__device__ float g_uin    [NV*256];
__device__ float g_uh     [NV*128];
__device__ float g_uh2    [NV*128];
__device__ float g_vraw   [NV*64];
__device__ int   g_deg    [2*NV];
__device__ int   g_off    [2*NV+1];
__device__ int   g_cur    [2*NV];
__device__ int   g_pcl    [NE];
__device__ float g_dw     [2*NV];
__device__ float g_vdw    [NV];
__device__ int   g_gcnt   [2*NG];
__device__ float g_stat   [2*NG*64];
__device__ float g_mean   [NG*64];
__device__ float g_rsig   [NG*64];
// tf32 weight copies (converted once per launch)
__device__ uint32_t g_qW0t[68*64];
__device__ uint32_t g_qW1t[64*64];
__device__ uint32_t g_cW0t[128*128];
__device__ uint32_t g_cW1t[128*128];
__device__ uint32_t g_uW0t[256*128];
__device__ uint32_t g_uW1t[128*128];
__device__ uint32_t g_uW2t[128*64];
__device__ uint32_t g_oW0t[64*64];

__device__ __forceinline__ float lrelu(float x){ return x > 0.f ? x : 0.2f*x; }
__device__ __forceinline__ float sp(float x){ return fmaxf(x,0.f) + log1pf(expf(-fabsf(x))); }
__device__ __forceinline__ uint32_t to_tf32(float x){
  uint32_t r; asm("cvt.rna.tf32.f32 %0, %1;" : "=r"(r) : "f"(x)); return r;
}
__device__ __forceinline__ void mma8(float* c, const uint32_t* a, const uint32_t* b){
  asm("mma.sync.aligned.m16n8k8.row.col.f32.tf32.tf32.f32 "
      "{%0,%1,%2,%3},{%4,%5,%6,%7},{%8,%9},{%0,%1,%2,%3};"
      : "+f"(c[0]),"+f"(c[1]),"+f"(c[2]),"+f"(c[3])
      : "r"(a[0]),"r"(a[1]),"r"(a[2]),"r"(a[3]), "r"(b[0]),"r"(b[1]));
}

// ----------------- setup -----------------
__global__ void k_setup0(){
  int i = blockIdx.x*blockDim.x + threadIdx.x, s = gridDim.x*blockDim.x;
  for(int j=i;j<2*NV;j+=s) g_deg[j]=0;
  if(i<2*NG) g_gcnt[i]=0;
}
__global__ void k_count(const int* __restrict__ lit, const int* __restrict__ vg,
                        const int* __restrict__ cg){
  int i = blockIdx.x*blockDim.x + threadIdx.x, s = gridDim.x*blockDim.x;
  for(int j=i;j<NE;j+=s) atomicAdd(&g_deg[lit[j]],1);
  for(int j=i;j<NV;j+=s) atomicAdd(&g_gcnt[NG+vg[j]],1);
  for(int j=i;j<NC;j+=s) atomicAdd(&g_gcnt[cg[j]],1);
}
// scan + degree weights (single block)
__global__ void k_scan(){
  __shared__ int sh[1024];
  __shared__ int carry;
  int tid = threadIdx.x;
  if(tid==0) carry=0;
  __syncthreads();
  for(int base=0; base<2*NV; base+=1024){
    int i = base + tid;
    int v = (i < 2*NV) ? g_deg[i] : 0;
    sh[tid] = v; __syncthreads();
    for(int d=1; d<1024; d<<=1){
      int t = (tid>=d) ? sh[tid-d] : 0;
      __syncthreads();
      sh[tid] += t;
      __syncthreads();
    }
    int excl = sh[tid] - v;
    int total = sh[1023];
    int c = carry;
    if(i < 2*NV){ g_off[i] = c + excl; g_cur[i] = c + excl; }
    __syncthreads();
    if(tid==0) carry = c + total;
    __syncthreads();
  }
  if(tid==0) g_off[2*NV] = carry;
  __syncthreads();
  for(int i=tid;i<2*NV;i+=1024) g_dw[i] = rsqrtf(fmaxf((float)g_deg[i],1.f));
  for(int i=tid;i<NV;i+=1024)  g_vdw[i] = 4.f*rsqrtf(fmaxf((float)(g_deg[i]+g_deg[NV+i]),1.f));
}
// CSR fill + state init
__global__ void k_fill(const int* __restrict__ lit){
  int i = blockIdx.x*blockDim.x + threadIdx.x, s = gridDim.x*blockDim.x;
  for(int e=i;e<NE;e+=s){
    int l = lit[e];
    int p = atomicAdd(&g_cur[l],1);
    g_pcl[p] = e/3;
  }
  for(int j=i;j<NV*64;j+=s) g_vars[j]=1.f;
  for(int j=i;j<NC*64;j+=s) g_clauses[j]=1.f;
}
// one-time tf32 conversion of all weights
__global__ void k_wconv(const float* q0,const float* q1,const float* c0,const float* c1,
                        const float* u0,const float* u1,const float* u2,const float* o0){
  int i = blockIdx.x*blockDim.x + threadIdx.x, s = gridDim.x*blockDim.x;
  for(int j=i;j<68*64;j+=s)   g_qW0t[j]=to_tf32(q0[j]);
  for(int j=i;j<64*64;j+=s)   g_qW1t[j]=to_tf32(q1[j]);
  for(int j=i;j<128*128;j+=s) g_cW0t[j]=to_tf32(c0[j]);
  for(int j=i;j<128*128;j+=s) g_cW1t[j]=to_tf32(c1[j]);
  for(int j=i;j<256*128;j+=s) g_uW0t[j]=to_tf32(u0[j]);
  for(int j=i;j<128*128;j+=s) g_uW1t[j]=to_tf32(u1[j]);
  for(int j=i;j<128*64;j+=s)  g_uW2t[j]=to_tf32(u2[j]);
  for(int j=i;j<64*64;j+=s)   g_oW0t[j]=to_tf32(o0[j]);
}
__global__ void k_zerof(float* __restrict__ p, int n){
  int i = blockIdx.x*blockDim.x + threadIdx.x;
  if(i<n) p[i]=0.f;
}

// ----------------- tensor-core MLP layer (tf32 mma.sync) -----------------
// C[M,N] = act(concat(A0[:,0:K0], s1*A1[:,0:K1]) @ W + b)
// ACT: 0=none, 1=leaky, 2=lits epilogue, 3=output head
// Block tile: 128 rows x N cols. 8 warps as RWxCW grid (4x2, or 8x1 for ACT3).
template<int K0,int K1,int N,int ACT>
__global__ void __launch_bounds__(256) k_mma(
    const float* __restrict__ A0, const float* __restrict__ A1, float s1,
    const uint32_t* __restrict__ Wt, const float* __restrict__ b,
    float* __restrict__ C, int M,
    const float* __restrict__ w2, const float* __restrict__ b2){
  constexpr int K  = K0 + K1;
  constexpr int KC = 32;
  constexpr int KP = KC + 4;      // sA pitch: stride 4 mod 32 -> A frag conflict-free
  constexpr int NP = N + 8;       // sW pitch: stride 8 mod 32 -> B frag conflict-free
  constexpr int NT = N / 8;
  constexpr int NCHUNK = (K + KC - 1) / KC;
  constexpr int CW = (ACT==3) ? 1 : 2;   // column warp-groups
  constexpr int RW = 8 / CW;             // row warp-groups
  constexpr int MF = (CW==2) ? 2 : 1;    // 16-row m-frags per warp
  constexpr int NW = NT / CW;            // 8-col n-tiles per warp
  __shared__ uint32_t sA[128*KP];
  __shared__ uint32_t sW[KC*NP];
  int tid = threadIdx.x;
  int w = tid >> 5, lane = tid & 31;
  int g = lane >> 2, tg = lane & 3;
  int wr = w % RW, wc = w / RW;
  int base = blockIdx.x * 128;
  int r0 = wr * 16 * MF;
  int cb = wc * NW * 8;
  float acc[MF][NW][4];
  #pragma unroll
  for(int j=0;j<NW;j++){
    int col = cb + j*8 + 2*tg;
    float b0v = b[col], b1v = b[col+1];
    #pragma unroll
    for(int mf=0;mf<MF;mf++){
      acc[mf][j][0]=b0v; acc[mf][j][1]=b1v; acc[mf][j][2]=b0v; acc[mf][j][3]=b1v;
    }
  }
  for(int ch=0; ch<NCHUNK; ch++){
    int k0 = ch*KC;
    int kc = K - k0; if(kc > KC) kc = KC;
    __syncthreads();
    // W chunk: vector copy of pre-converted tf32 (zero-pad kk>=kc)
    for(int i=tid; i<KC*(N/4); i+=256){
      int kk = i/(N/4), nq = i%(N/4);
      uint4 v = make_uint4(0u,0u,0u,0u);
      if(kk < kc) v = *(const uint4*)&Wt[(size_t)(k0+kk)*N + nq*4];
      *(uint4*)&sW[kk*NP + nq*4] = v;
    }
    // A chunk: vector load + cvt (zero-pad)
    for(int i=tid; i<128*(KC/4); i+=256){
      int r = i >> 3, kq = i & 7;
      int row = base + r, col = k0 + kq*4;
      uint4 u = make_uint4(0u,0u,0u,0u);
      if(row < M && kq*4 < kc){
        float4 v;
        if(col < K0) v = *(const float4*)&A0[(size_t)row*K0 + col];
        else {
          v = *(const float4*)&A1[(size_t)row*K1 + (col - K0)];
          v.x*=s1; v.y*=s1; v.z*=s1; v.w*=s1;
        }
        u.x=to_tf32(v.x); u.y=to_tf32(v.y); u.z=to_tf32(v.z); u.w=to_tf32(v.w);
      }
      *(uint4*)&sA[r*KP + kq*4] = u;
    }
    __syncthreads();
    #pragma unroll
    for(int s=0;s<KC/8;s++){
      int ks = s*8;
      uint32_t a[MF][4];
      #pragma unroll
      for(int mf=0;mf<MF;mf++){
        int rr = r0 + mf*16;
        a[mf][0] = sA[(rr + g    )*KP + ks + tg];
        a[mf][1] = sA[(rr + g + 8)*KP + ks + tg];
        a[mf][2] = sA[(rr + g    )*KP + ks + tg + 4];
        a[mf][3] = sA[(rr + g + 8)*KP + ks + tg + 4];
      }
      #pragma unroll
      for(int j=0;j<NW;j++){
        uint32_t bb[2];
        int col = cb + j*8 + g;
        bb[0] = sW[(ks + tg    )*NP + col];
        bb[1] = sW[(ks + tg + 4)*NP + col];
        #pragma unroll
        for(int mf=0;mf<MF;mf++) mma8(acc[mf][j], a[mf], bb);
      }
    }
  }
  // epilogues
  if(ACT==0 || ACT==1){
    #pragma unroll
    for(int mf=0;mf<MF;mf++){
      int row0 = base + r0 + mf*16 + g;
      int row1 = row0 + 8;
      #pragma unroll
      for(int j=0;j<NW;j++){
        int col = cb + j*8 + 2*tg;
        float2 o0, o1;
        o0.x = (ACT==1)? lrelu(acc[mf][j][0]) : acc[mf][j][0];
        o0.y = (ACT==1)? lrelu(acc[mf][j][1]) : acc[mf][j][1];
        o1.x = (ACT==1)? lrelu(acc[mf][j][2]) : acc[mf][j][2];
        o1.y = (ACT==1)? lrelu(acc[mf][j][3]) : acc[mf][j][3];
        if(row0 < M) *(float2*)&C[(size_t)row0*N + col] = o0;
        if(row1 < M) *(float2*)&C[(size_t)row1*N + col] = o1;
      }
    }
  } else if(ACT==2){
    #pragma unroll
    for(int mf=0;mf<MF;mf++){
      #pragma unroll
      for(int j=0;j<NW;j++){
        int col = cb + j*8 + 2*tg;
        #pragma unroll
        for(int h=0;h<2;h++){
          int row = base + r0 + mf*16 + g + 8*h;
          if(row < M){
            float qa = acc[mf][j][2*h], qb = acc[mf][j][2*h+1];
            float2 lp = make_float2(sp(qa), sp(qb));
            float2 ln = make_float2(sp(-qa), sp(-qb));
            float2 sg = make_float2(1.f/(1.f+expf(-qa)), 1.f/(1.f+expf(-qb)));
            *(float2*)&g_lits[(size_t)row*64 + col]      = lp;
            *(float2*)&g_lits[(size_t)(NV+row)*64 + col] = ln;
            *(float2*)&g_sig [(size_t)row*64 + col]      = sg;
          }
        }
      }
    }
  } else { // ACT==3 (CW=1): head
    float p0 = 0.f, p1 = 0.f;
    #pragma unroll
    for(int j=0;j<NW;j++){
      int col = j*8 + 2*tg;
      float wa = w2[col], wb = w2[col+1];
      p0 += lrelu(acc[0][j][0])*wa + lrelu(acc[0][j][1])*wb;
      p1 += lrelu(acc[0][j][2])*wa + lrelu(acc[0][j][3])*wb;
    }
    #pragma unroll
    for(int o=2;o>0;o>>=1){
      p0 += __shfl_down_sync(0xffffffffu, p0, o, 4);
      p1 += __shfl_down_sync(0xffffffffu, p1, o, 4);
    }
    if(tg == 0){
      int row0 = base + r0 + g;
      int row1 = row0 + 8;
      float bb = b2[0];
      if(row0 < M){
        float lg = p0 + bb;
        C[row0] = 1.f/(1.f+expf(-lg)); C[NC + row0] = sp(lg);
      }
      if(row1 < M){
        float lg = p1 + bb;
        C[row1] = 1.f/(1.f+expf(-lg)); C[NC + row1] = sp(lg);
      }
    }
  }
}

// ----------------- per-round graph kernels -----------------
__global__ void k_cl(const int* __restrict__ lit){
  int idx = blockIdx.x*blockDim.x + threadIdx.x;
  if(idx >= NC*16) return;
  int c = idx >> 4, q = (idx & 15) * 4;
  int e = 3*c;
  int l0 = lit[e], l1 = lit[e+1], l2 = lit[e+2];
  float4 A = *(const float4*)&g_lits[(size_t)l0*64 + q];
  float4 B = *(const float4*)&g_lits[(size_t)l1*64 + q];
  float4 C = *(const float4*)&g_lits[(size_t)l2*64 + q];
  float4 o;
  o.x = expf(-(A.x+B.x+C.x)); o.y = expf(-(A.y+B.y+C.y));
  o.z = expf(-(A.z+B.z+C.z)); o.w = expf(-(A.w+B.w+C.w));
  *(float4*)&g_cl[(size_t)c*64 + q] = o;
}

__global__ void __launch_bounds__(256) k_uin(){
  int tid = threadIdx.x;
  int f = tid & 63;
  int v = blockIdx.x*4 + (tid >> 6);
  if(v >= NV) return;
  int p0 = g_off[v],    p1 = g_off[v+1];
  int n0 = g_off[NV+v], n1 = g_off[NV+v+1];
  float scl=0.f, scd=0.f, ncl=0.f, ncd=0.f;
  for(int e=p0;e<p1;e++){
    int c = g_pcl[e];
    scl += g_cl[(size_t)c*64 + f];
    scd += g_cd[(size_t)c*128 + f];
  }
  for(int e=n0;e<n1;e++){
    int c = g_pcl[e];
    ncl += g_cl[(size_t)c*64 + f];
    ncd += g_cd[(size_t)c*128 + f];
  }
  float sg = g_sig[(size_t)v*64 + f];
  float gr = (-sg*scl + (1.f-sg)*ncl) * g_vdw[v];
  size_t o = (size_t)v*256;
  g_uin[o + f]       = gr;
  g_uin[o + 64 + f]  = g_vars[(size_t)v*64 + f];
  g_uin[o + 128 + f] = scd * g_dw[v];
  g_uin[o + 192 + f] = ncd * g_dw[NV+v];
}

// ----------------- pair-norm -----------------
__global__ void k_stats(const float* __restrict__ src, int S, int off,
                        const int* __restrict__ gid, int n){
  __shared__ float s1[256], s2[256];
  int tid = threadIdx.x;
  int f = tid & 63, lane = tid >> 6;
  int row0 = blockIdx.x * 64;
  int rend = min(row0 + 64, n);
  int g0 = gid[row0], g1 = gid[rend-1];
  if(g0 == g1){
    float s = 0.f, q = 0.f;
    for(int r = row0 + lane; r < rend; r += 4){
      float x = src[(size_t)r*S + off + f];
      s += x; q += x*x;
    }
    s1[tid] = s; s2[tid] = q;
    __syncthreads();
    if(lane == 0){
      s = s1[f] + s1[64+f] + s1[128+f] + s1[192+f];
      q = s2[f] + s2[64+f] + s2[128+f] + s2[192+f];
      atomicAdd(&g_stat[g0*64 + f], s);
      atomicAdd(&g_stat[NG*64 + g0*64 + f], q);
    }
  } else {
    for(int r = row0 + lane; r < rend; r += 4){
      float x = src[(size_t)r*S + off + f];
      int g = gid[r];
      atomicAdd(&g_stat[g*64 + f], x);
      atomicAdd(&g_stat[NG*64 + g*64 + f], x*x);
    }
  }
}
__global__ void k_fin(int cntoff){
  int i = blockIdx.x*blockDim.x + threadIdx.x;
  if(i >= NG*64) return;
  int g = i >> 6;
  float inv = 1.f / fmaxf((float)g_gcnt[cntoff + g], 1.f);
  float m = g_stat[i] * inv;
  float var = g_stat[NG*64 + i] * inv - m*m;
  g_mean[i] = m;
  g_rsig[i] = rsqrtf(fmaxf(var, 0.f) + 1e-6f);
}
__global__ void k_apply(const float* __restrict__ src, int S, int off,
                        float* __restrict__ target, const int* __restrict__ gid, int n){
  int i = blockIdx.x*blockDim.x + threadIdx.x;
  if(i >= n*64) return;
  int r = i >> 6, f = i & 63;
  int g = gid[r];
  float x = src[(size_t)r*S + off + f];
  float y = (x - g_mean[g*64+f]) * g_rsig[g*64+f] * 0.25f;
  target[i] = y + 0.1f * target[i];
}

// ----------------- host -----------------
static float* fsym(const void* s){ void* p=nullptr; cudaGetSymbolAddress(&p, s); return (float*)p; }
static uint32_t* usym(const void* s){ void* p=nullptr; cudaGetSymbolAddress(&p, s); return (uint32_t*)p; }

extern "C" void kernel_launch(void* const* d_in, const int* in_sizes, int n_in,
                              void* d_out, int out_size){
  const int*   lit   = (const int*)d_in[0];
  const int*   vg    = (const int*)d_in[2];
  const int*   cg    = (const int*)d_in[3];
  const float* noise = (const float*)d_in[4];
  const float *qW0=(const float*)d_in[5],  *qb0=(const float*)d_in[6];
  const float *qW1=(const float*)d_in[7],  *qb1=(const float*)d_in[8];
  const float *cW0=(const float*)d_in[9],  *cb0=(const float*)d_in[10];
  const float *cW1=(const float*)d_in[11], *cb1=(const float*)d_in[12];
  const float *uW0=(const float*)d_in[13], *ub0=(const float*)d_in[14];
  const float *uW1=(const float*)d_in[15], *ub1=(const float*)d_in[16];
  const float *uW2=(const float*)d_in[17], *ub2=(const float*)d_in[18];
  const float *oW0=(const float*)d_in[19], *ob0=(const float*)d_in[20];
  const float *oW1=(const float*)d_in[21], *ob1=(const float*)d_in[22];
  float* out = (float*)d_out;

  float *p_qh   = fsym(g_qh);
  float *p_ch   = fsym(g_ch),  *p_cd   = fsym(g_cd),  *p_cl = fsym(g_cl);
  float *p_uin  = fsym(g_uin), *p_uh   = fsym(g_uh),  *p_uh2 = fsym(g_uh2);
  float *p_vraw = fsym(g_vraw),*p_vars = fsym(g_vars);
  float *p_claus= fsym(g_clauses);
  float *p_stat = fsym(g_stat);
  uint32_t *t_q0 = usym(g_qW0t), *t_q1 = usym(g_qW1t);
  uint32_t *t_c0 = usym(g_cW0t), *t_c1 = usym(g_cW1t);
  uint32_t *t_u0 = usym(g_uW0t), *t_u1 = usym(g_uW1t), *t_u2 = usym(g_uW2t);
  uint32_t *t_o0 = usym(g_oW0t);

  const int T = 256;
  auto B = [](long n){ return (int)((n + 255) / 256); };
  int mbV = (NV + 127) / 128, mbC = (NC + 127) / 128;
  int gbV = (NV + 63) / 64,   gbC = (NC + 63) / 64;

  // setup (5 launches so ncu -s 5 captures the first k_mma)
  k_setup0<<<256, T>>>();
  k_count<<<1024, T>>>(lit, vg, cg);
  k_scan<<<1, 1024>>>();
  k_fill<<<1024, T>>>(lit);
  k_wconv<<<256, T>>>(qW0, qW1, cW0, cW1, uW0, uW1, uW2, oW0);

  for(int t = 0; t < ROUNDS; t++){
    const float* nz = noise + (size_t)t * NV * 4;
    k_mma<64,4,64,1><<<mbV, T>>>(p_vars, nz, 1.f, t_q0, qb0, p_qh, NV, nullptr, nullptr);
    k_mma<64,0,64,2><<<mbV, T>>>(p_qh, nullptr, 0.f, t_q1, qb1, nullptr, NV, nullptr, nullptr);
    k_cl<<<B((long)NC*16), T>>>(lit);

    k_mma<64,64,128,1><<<mbC, T>>>(p_claus, p_cl, 4.f, t_c0, cb0, p_ch, NC, nullptr, nullptr);
    k_mma<128,0,128,0><<<mbC, T>>>(p_ch, nullptr, 0.f, t_c1, cb1, p_cd, NC, nullptr, nullptr);

    k_zerof<<<B(2L*NG*64), T>>>(p_stat, 2*NG*64);
    k_stats<<<gbC, T>>>(p_cd, 128, 64, cg, NC);
    k_fin<<<8, T>>>(0);
    k_apply<<<B((long)NC*64), T>>>(p_cd, 128, 64, p_claus, cg, NC);

    k_uin<<<(NV+3)/4, T>>>();

    k_mma<256,0,128,1><<<mbV, T>>>(p_uin, nullptr, 0.f, t_u0, ub0, p_uh, NV, nullptr, nullptr);
    k_mma<128,0,128,1><<<mbV, T>>>(p_uh,  nullptr, 0.f, t_u1, ub1, p_uh2, NV, nullptr, nullptr);
    k_mma<128,0,64,0 ><<<mbV, T>>>(p_uh2, nullptr, 0.f, t_u2, ub2, p_vraw, NV, nullptr, nullptr);

    k_zerof<<<B(2L*NG*64), T>>>(p_stat, 2*NG*64);
    k_stats<<<gbV, T>>>(p_vraw, 64, 0, vg, NV);
    k_fin<<<8, T>>>(NG);
    k_apply<<<B((long)NV*64), T>>>(p_vraw, 64, 0, p_vars, vg, NV);
  }

  k_mma<64,0,64,3><<<mbC, T>>>(p_claus, nullptr, 0.f, t_o0, ob0, out, NC, oW1, ob1);

  (void)in_sizes; (void)n_in; (void)out_size;
}

// round 9
// speedup vs baseline: 3.9504x; 1.5503x over previous
#include <cuda_runtime.h>
#include <cuda_fp16.h>
#include <math.h>
#include <stdint.h>

constexpr int NV = 50000, NC = 210000, NE = 630000, NG = 32, ROUNDS = 16;

// ----------------- device scratch -----------------
__device__ float  g_vars   [NV*64];     // recurrent state fp32
__device__ float  g_clauses[NC*64];     // recurrent state fp32
__device__ __half g_qh     [NV*64];
__device__ __half g_lits   [2*NV*64];
__device__ __half g_sig    [NV*64];
__device__ __half g_cl     [NC*64];
__device__ __half g_ch     [NC*128];
__device__ __half g_cd     [NC*128];
__device__ __half g_uin    [NV*256];
__device__ __half g_uh     [NV*128];
__device__ __half g_uh2    [NV*128];
__device__ __half g_vraw   [NV*64];
__device__ int    g_deg    [2*NV];
__device__ int    g_off    [2*NV+1];
__device__ int    g_cur    [2*NV];
__device__ int    g_pcl    [NE];
__device__ float  g_dw     [2*NV];
__device__ float  g_vdw    [NV];
__device__ int    g_gcnt   [2*NG];
__device__ float  g_stat   [2*NG*64];
__device__ float  g_mean   [NG*64];
__device__ float  g_rsig   [NG*64];
// fp16 weights, TRANSPOSED [n][k] with k padded to multiple of 8
__device__ __half g_qW0h[64*72];
__device__ __half g_qW1h[64*64];
__device__ __half g_cW0h[128*128];
__device__ __half g_cW1h[128*128];
__device__ __half g_uW0h[128*256];
__device__ __half g_uW1h[128*128];
__device__ __half g_uW2h[64*128];
__device__ __half g_oW0h[64*64];

__device__ __forceinline__ float lrelu(float x){ return x > 0.f ? x : 0.2f*x; }
__device__ __forceinline__ float sp(float x){ return fmaxf(x,0.f) + log1pf(expf(-fabsf(x))); }

__device__ __forceinline__ void mma16(float* c, const uint32_t* a, const uint32_t* b){
  asm("mma.sync.aligned.m16n8k16.row.col.f32.f16.f16.f32 "
      "{%0,%1,%2,%3},{%4,%5,%6,%7},{%8,%9},{%0,%1,%2,%3};"
      : "+f"(c[0]),"+f"(c[1]),"+f"(c[2]),"+f"(c[3])
      : "r"(a[0]),"r"(a[1]),"r"(a[2]),"r"(a[3]),"r"(b[0]),"r"(b[1]));
}
__device__ __forceinline__ void ldmA4(uint32_t* a, uint32_t addr){
  asm volatile("ldmatrix.sync.aligned.m8n8.x4.shared.b16 {%0,%1,%2,%3}, [%4];"
    : "=r"(a[0]),"=r"(a[1]),"=r"(a[2]),"=r"(a[3]) : "r"(addr));
}
__device__ __forceinline__ void ldmB2(uint32_t* b, uint32_t addr){
  asm volatile("ldmatrix.sync.aligned.m8n8.x2.shared.b16 {%0,%1}, [%2];"
    : "=r"(b[0]),"=r"(b[1]) : "r"(addr));
}
// load 8 consecutive source elems -> 4 half2
__device__ __forceinline__ void load8(const float* A, size_t off, float s, __half2* h){
  float4 v0 = *(const float4*)(A+off), v1 = *(const float4*)(A+off+4);
  h[0]=__floats2half2_rn(v0.x*s, v0.y*s); h[1]=__floats2half2_rn(v0.z*s, v0.w*s);
  h[2]=__floats2half2_rn(v1.x*s, v1.y*s); h[3]=__floats2half2_rn(v1.z*s, v1.w*s);
}
__device__ __forceinline__ void load8(const __half* A, size_t off, float s, __half2* h){
  uint4 u = *(const uint4*)(A+off);
  __half2* p = (__half2*)&u;
  if(s == 1.f){ h[0]=p[0]; h[1]=p[1]; h[2]=p[2]; h[3]=p[3]; }
  else {
    __half2 sc = __float2half2_rn(s);
    h[0]=__hmul2(p[0],sc); h[1]=__hmul2(p[1],sc);
    h[2]=__hmul2(p[2],sc); h[3]=__hmul2(p[3],sc);
  }
}
__device__ __forceinline__ float ldA1(const float* A, size_t i){ return A[i]; }
__device__ __forceinline__ float ldA1(const __half* A, size_t i){ return __half2float(A[i]); }

// ----------------- setup -----------------
__global__ void k_setup0(){
  int i = blockIdx.x*blockDim.x + threadIdx.x, s = gridDim.x*blockDim.x;
  for(int j=i;j<2*NV;j+=s) g_deg[j]=0;
  if(i<2*NG) g_gcnt[i]=0;
}
__global__ void k_count(const int* __restrict__ lit, const int* __restrict__ vg,
                        const int* __restrict__ cg){
  int i = blockIdx.x*blockDim.x + threadIdx.x, s = gridDim.x*blockDim.x;
  for(int j=i;j<NE;j+=s) atomicAdd(&g_deg[lit[j]],1);
  for(int j=i;j<NV;j+=s) atomicAdd(&g_gcnt[NG+vg[j]],1);
  for(int j=i;j<NC;j+=s) atomicAdd(&g_gcnt[cg[j]],1);
}
__global__ void k_scan(){
  __shared__ int sh[1024];
  __shared__ int carry;
  int tid = threadIdx.x;
  if(tid==0) carry=0;
  __syncthreads();
  for(int base=0; base<2*NV; base+=1024){
    int i = base + tid;
    int v = (i < 2*NV) ? g_deg[i] : 0;
    sh[tid] = v; __syncthreads();
    for(int d=1; d<1024; d<<=1){
      int t = (tid>=d) ? sh[tid-d] : 0;
      __syncthreads();
      sh[tid] += t;
      __syncthreads();
    }
    int excl = sh[tid] - v;
    int total = sh[1023];
    int c = carry;
    if(i < 2*NV){ g_off[i] = c + excl; g_cur[i] = c + excl; }
    __syncthreads();
    if(tid==0) carry = c + total;
    __syncthreads();
  }
  if(tid==0) g_off[2*NV] = carry;
  __syncthreads();
  for(int i=tid;i<2*NV;i+=1024) g_dw[i] = rsqrtf(fmaxf((float)g_deg[i],1.f));
  for(int i=tid;i<NV;i+=1024)  g_vdw[i] = 4.f*rsqrtf(fmaxf((float)(g_deg[i]+g_deg[NV+i]),1.f));
}
__global__ void k_fill(const int* __restrict__ lit){
  int i = blockIdx.x*blockDim.x + threadIdx.x, s = gridDim.x*blockDim.x;
  for(int e=i;e<NE;e+=s){
    int l = lit[e];
    int p = atomicAdd(&g_cur[l],1);
    g_pcl[p] = e/3;
  }
  for(int j=i;j<NV*64;j+=s) g_vars[j]=1.f;
  for(int j=i;j<NC*64;j+=s) g_clauses[j]=1.f;
}
// transpose+pad+convert one matrix
__device__ void wtconv(const float* W, __half* WT, int K, int N, int Kp, int i, int s){
  for(int j=i;j<N*Kp;j+=s){
    int n = j/Kp, k = j%Kp;
    WT[j] = __float2half_rn((k < K) ? W[(size_t)k*N + n] : 0.f);
  }
}
__global__ void k_wconv(const float* q0,const float* q1,const float* c0,const float* c1,
                        const float* u0,const float* u1,const float* u2,const float* o0){
  int i = blockIdx.x*blockDim.x + threadIdx.x, s = gridDim.x*blockDim.x;
  wtconv(q0, g_qW0h,  68,  64,  72, i, s);
  wtconv(q1, g_qW1h,  64,  64,  64, i, s);
  wtconv(c0, g_cW0h, 128, 128, 128, i, s);
  wtconv(c1, g_cW1h, 128, 128, 128, i, s);
  wtconv(u0, g_uW0h, 256, 128, 256, i, s);
  wtconv(u1, g_uW1h, 128, 128, 128, i, s);
  wtconv(u2, g_uW2h, 128,  64, 128, i, s);
  wtconv(o0, g_oW0h,  64,  64,  64, i, s);
}
__global__ void k_zerof(float* __restrict__ p, int n){
  int i = blockIdx.x*blockDim.x + threadIdx.x;
  if(i<n) p[i]=0.f;
}

// ----------------- fp16 tensor-core MLP layer -----------------
// out = act(concat(A0[:,0:K0], s1*A1[:,0:K1]) @ W + b)
// ACT: 0=none(half out), 1=leaky(half out), 2=lits epilogue, 3=output head(float out)
template<typename T0, typename T1, int K0,int K1,int N,int ACT>
__global__ void __launch_bounds__(256) k_mma(
    const T0* __restrict__ A0, const T1* __restrict__ A1, float s1,
    const __half* __restrict__ WT, const float* __restrict__ b,
    void* Cv, int M, const float* __restrict__ w2, const float* __restrict__ b2){
  constexpr int K  = K0 + K1;
  constexpr int Kp = (K + 7) & ~7;
  constexpr int KC = 64;
  constexpr int PH = KC + 8;                 // 72 halfs/row = 144B pitch (ldmatrix conflict-free)
  constexpr int NCHUNK = (K + KC - 1) / KC;
  constexpr int NT = N / 8;
  constexpr int CW = (ACT==3) ? 1 : 2;
  constexpr int RW = 8 / CW;
  constexpr int MF = 128 / (16*RW);
  constexpr int NW = NT / CW;
  __shared__ __align__(16) __half sA[128*PH];
  __shared__ __align__(16) __half sW[N*PH];
  int tid = threadIdx.x;
  int w = tid >> 5, lane = tid & 31;
  int g = lane >> 2, tg = lane & 3;
  int wr = w % RW, wc = w / RW;
  int base = blockIdx.x * 128;
  int r0 = wr * 16 * MF;
  int cb = wc * NW * 8;
  float acc[MF][NW][4];
  #pragma unroll
  for(int j=0;j<NW;j++){
    int col = cb + j*8 + 2*tg;
    float b0v = b[col], b1v = b[col+1];
    #pragma unroll
    for(int mf=0;mf<MF;mf++){
      acc[mf][j][0]=b0v; acc[mf][j][1]=b1v; acc[mf][j][2]=b0v; acc[mf][j][3]=b1v;
    }
  }
  uint32_t sAb = (uint32_t)__cvta_generic_to_shared(sA);
  uint32_t sWb = (uint32_t)__cvta_generic_to_shared(sW);
  for(int ch=0; ch<NCHUNK; ch++){
    int k0c = ch*KC;
    __syncthreads();
    // W chunk (rows = n, k contiguous, pre-transposed fp16)
    for(int i=tid; i<N*(KC/8); i+=256){
      int n = i/(KC/8), kg = i%(KC/8);
      int col0 = k0c + kg*8;
      uint4 u = make_uint4(0u,0u,0u,0u);
      if(col0 + 8 <= Kp) u = *(const uint4*)&WT[(size_t)n*Kp + col0];
      *(uint4*)&sW[n*PH + kg*8] = u;
    }
    // A chunk
    for(int i=tid; i<128*(KC/8); i+=256){
      int r = i/(KC/8), kg = i%(KC/8);
      int col0 = k0c + kg*8;
      int row = base + r;
      __half2 h[4];
      h[0]=h[1]=h[2]=h[3]=__float2half2_rn(0.f);
      if(row < M){
        if(col0 + 8 <= K0) load8(A0, (size_t)row*K0 + col0, 1.f, h);
        else if(col0 >= K0 && col0 + 8 <= K0+K1) load8(A1, (size_t)row*K1 + (col0-K0), s1, h);
        else if(col0 < K0+K1){
          float t[8];
          #pragma unroll
          for(int e=0;e<8;e++){
            int c = col0 + e; float x = 0.f;
            if(c < K0) x = ldA1(A0, (size_t)row*K0 + c);
            else if(c < K0+K1) x = s1 * ldA1(A1, (size_t)row*K1 + (c-K0));
            t[e] = x;
          }
          h[0]=__floats2half2_rn(t[0],t[1]); h[1]=__floats2half2_rn(t[2],t[3]);
          h[2]=__floats2half2_rn(t[4],t[5]); h[3]=__floats2half2_rn(t[6],t[7]);
        }
      }
      *(uint4*)&sA[r*PH + kg*8] = *(uint4*)h;
    }
    __syncthreads();
    int lr = lane & 7;
    #pragma unroll
    for(int s=0;s<KC/16;s++){
      int ks = s*16;
      uint32_t bfr[NW][2];
      #pragma unroll
      for(int j=0;j<NW;j++){
        int nrow = cb + j*8 + lr;
        int kcol = ks + ((lane>>3)&1)*8;
        ldmB2(bfr[j], sWb + (uint32_t)(nrow*PH + kcol)*2);
      }
      uint32_t afr[MF][4];
      #pragma unroll
      for(int mf=0;mf<MF;mf++){
        int row = r0 + mf*16 + lr + ((lane>>3)&1)*8;
        int kcol = ks + ((lane>>4)&1)*8;
        ldmA4(afr[mf], sAb + (uint32_t)(row*PH + kcol)*2);
      }
      #pragma unroll
      for(int mf=0;mf<MF;mf++)
        #pragma unroll
        for(int j=0;j<NW;j++) mma16(acc[mf][j], afr[mf], bfr[j]);
    }
  }
  // epilogues
  if(ACT==0 || ACT==1){
    __half* C = (__half*)Cv;
    #pragma unroll
    for(int mf=0;mf<MF;mf++){
      int row0 = base + r0 + mf*16 + g;
      int row1 = row0 + 8;
      #pragma unroll
      for(int j=0;j<NW;j++){
        int col = cb + j*8 + 2*tg;
        float a0 = acc[mf][j][0], a1 = acc[mf][j][1];
        float a2 = acc[mf][j][2], a3 = acc[mf][j][3];
        if(ACT==1){ a0=lrelu(a0); a1=lrelu(a1); a2=lrelu(a2); a3=lrelu(a3); }
        if(row0 < M) *(__half2*)&C[(size_t)row0*N + col] = __floats2half2_rn(a0,a1);
        if(row1 < M) *(__half2*)&C[(size_t)row1*N + col] = __floats2half2_rn(a2,a3);
      }
    }
  } else if(ACT==2){
    #pragma unroll
    for(int mf=0;mf<MF;mf++){
      #pragma unroll
      for(int j=0;j<NW;j++){
        int col = cb + j*8 + 2*tg;
        #pragma unroll
        for(int h=0;h<2;h++){
          int row = base + r0 + mf*16 + g + 8*h;
          if(row < M){
            float qa = acc[mf][j][2*h], qb = acc[mf][j][2*h+1];
            *(__half2*)&g_lits[(size_t)row*64 + col]      = __floats2half2_rn(sp(qa), sp(qb));
            *(__half2*)&g_lits[(size_t)(NV+row)*64 + col] = __floats2half2_rn(sp(-qa), sp(-qb));
            *(__half2*)&g_sig [(size_t)row*64 + col]      =
                __floats2half2_rn(1.f/(1.f+expf(-qa)), 1.f/(1.f+expf(-qb)));
          }
        }
      }
    }
  } else { // ACT==3 (CW=1)
    float* C = (float*)Cv;
    float p0 = 0.f, p1 = 0.f;
    #pragma unroll
    for(int j=0;j<NW;j++){
      int col = j*8 + 2*tg;
      float wa = w2[col], wb = w2[col+1];
      p0 += lrelu(acc[0][j][0])*wa + lrelu(acc[0][j][1])*wb;
      p1 += lrelu(acc[0][j][2])*wa + lrelu(acc[0][j][3])*wb;
    }
    #pragma unroll
    for(int o=2;o>0;o>>=1){
      p0 += __shfl_down_sync(0xffffffffu, p0, o, 4);
      p1 += __shfl_down_sync(0xffffffffu, p1, o, 4);
    }
    if(tg == 0){
      int row0 = base + r0 + g;
      int row1 = row0 + 8;
      float bb = b2[0];
      if(row0 < M){
        float lg = p0 + bb;
        C[row0] = 1.f/(1.f+expf(-lg)); C[NC + row0] = sp(lg);
      }
      if(row1 < M){
        float lg = p1 + bb;
        C[row1] = 1.f/(1.f+expf(-lg)); C[NC + row1] = sp(lg);
      }
    }
  }
}

// ----------------- per-round graph kernels (fp16 buffers) -----------------
__global__ void k_cl(const int* __restrict__ lit){
  int idx = blockIdx.x*blockDim.x + threadIdx.x;
  if(idx >= NC*8) return;
  int c = idx >> 3, q = (idx & 7) * 8;
  int e = 3*c;
  int l0 = lit[e], l1 = lit[e+1], l2 = lit[e+2];
  uint4 ua = *(const uint4*)&g_lits[(size_t)l0*64 + q];
  uint4 ub = *(const uint4*)&g_lits[(size_t)l1*64 + q];
  uint4 uc = *(const uint4*)&g_lits[(size_t)l2*64 + q];
  __half2* pa = (__half2*)&ua; __half2* pb = (__half2*)&ub; __half2* pc = (__half2*)&uc;
  __half2 o[4];
  #pragma unroll
  for(int p=0;p<4;p++){
    float2 fa = __half22float2(pa[p]), fb = __half22float2(pb[p]), fc = __half22float2(pc[p]);
    o[p] = __floats2half2_rn(expf(-(fa.x+fb.x+fc.x)), expf(-(fa.y+fb.y+fc.y)));
  }
  *(uint4*)&g_cl[(size_t)c*64 + q] = *(uint4*)o;
}

__global__ void __launch_bounds__(256) k_uin(){
  int tid = threadIdx.x;
  int f = tid & 63;
  int v = blockIdx.x*4 + (tid >> 6);
  if(v >= NV) return;
  int p0 = g_off[v],    p1 = g_off[v+1];
  int n0 = g_off[NV+v], n1 = g_off[NV+v+1];
  float scl=0.f, scd=0.f, ncl=0.f, ncd=0.f;
  for(int e=p0;e<p1;e++){
    int c = g_pcl[e];
    scl += __half2float(g_cl[(size_t)c*64 + f]);
    scd += __half2float(g_cd[(size_t)c*128 + f]);
  }
  for(int e=n0;e<n1;e++){
    int c = g_pcl[e];
    ncl += __half2float(g_cl[(size_t)c*64 + f]);
    ncd += __half2float(g_cd[(size_t)c*128 + f]);
  }
  float sg = __half2float(g_sig[(size_t)v*64 + f]);
  float gr = (-sg*scl + (1.f-sg)*ncl) * g_vdw[v];
  size_t o = (size_t)v*256;
  g_uin[o + f]       = __float2half_rn(gr);
  g_uin[o + 64 + f]  = __float2half_rn(g_vars[(size_t)v*64 + f]);
  g_uin[o + 128 + f] = __float2half_rn(scd * g_dw[v]);
  g_uin[o + 192 + f] = __float2half_rn(ncd * g_dw[NV+v]);
}

// ----------------- pair-norm (half src, float state) -----------------
__global__ void k_stats(const __half* __restrict__ src, int S, int off,
                        const int* __restrict__ gid, int n){
  __shared__ float s1[256], s2[256];
  int tid = threadIdx.x;
  int f = tid & 63, lane = tid >> 6;
  int row0 = blockIdx.x * 64;
  int rend = min(row0 + 64, n);
  int g0 = gid[row0], g1 = gid[rend-1];
  if(g0 == g1){
    float s = 0.f, q = 0.f;
    for(int r = row0 + lane; r < rend; r += 4){
      float x = __half2float(src[(size_t)r*S + off + f]);
      s += x; q += x*x;
    }
    s1[tid] = s; s2[tid] = q;
    __syncthreads();
    if(lane == 0){
      s = s1[f] + s1[64+f] + s1[128+f] + s1[192+f];
      q = s2[f] + s2[64+f] + s2[128+f] + s2[192+f];
      atomicAdd(&g_stat[g0*64 + f], s);
      atomicAdd(&g_stat[NG*64 + g0*64 + f], q);
    }
  } else {
    for(int r = row0 + lane; r < rend; r += 4){
      float x = __half2float(src[(size_t)r*S + off + f]);
      int g = gid[r];
      atomicAdd(&g_stat[g*64 + f], x);
      atomicAdd(&g_stat[NG*64 + g*64 + f], x*x);
    }
  }
}
__global__ void k_fin(int cntoff){
  int i = blockIdx.x*blockDim.x + threadIdx.x;
  if(i >= NG*64) return;
  int g = i >> 6;
  float inv = 1.f / fmaxf((float)g_gcnt[cntoff + g], 1.f);
  float m = g_stat[i] * inv;
  float var = g_stat[NG*64 + i] * inv - m*m;
  g_mean[i] = m;
  g_rsig[i] = rsqrtf(fmaxf(var, 0.f) + 1e-6f);
}
__global__ void k_apply(const __half* __restrict__ src, int S, int off,
                        float* __restrict__ target, const int* __restrict__ gid, int n){
  int i = blockIdx.x*blockDim.x + threadIdx.x;
  if(i >= n*64) return;
  int r = i >> 6, f = i & 63;
  int g = gid[r];
  float x = __half2float(src[(size_t)r*S + off + f]);
  float y = (x - g_mean[g*64+f]) * g_rsig[g*64+f] * 0.25f;
  target[i] = y + 0.1f * target[i];
}

// ----------------- host -----------------
static void* sym(const void* s){ void* p=nullptr; cudaGetSymbolAddress(&p, s); return p; }

extern "C" void kernel_launch(void* const* d_in, const int* in_sizes, int n_in,
                              void* d_out, int out_size){
  const int*   lit   = (const int*)d_in[0];
  const int*   vg    = (const int*)d_in[2];
  const int*   cg    = (const int*)d_in[3];
  const float* noise = (const float*)d_in[4];
  const float *qW0=(const float*)d_in[5],  *qb0=(const float*)d_in[6];
  const float *qW1=(const float*)d_in[7],  *qb1=(const float*)d_in[8];
  const float *cW0=(const float*)d_in[9],  *cb0=(const float*)d_in[10];
  const float *cW1=(const float*)d_in[11], *cb1=(const float*)d_in[12];
  const float *uW0=(const float*)d_in[13], *ub0=(const float*)d_in[14];
  const float *uW1=(const float*)d_in[15], *ub1=(const float*)d_in[16];
  const float *uW2=(const float*)d_in[17], *ub2=(const float*)d_in[18];
  const float *oW0=(const float*)d_in[19], *ob0=(const float*)d_in[20];
  const float *oW1=(const float*)d_in[21], *ob1=(const float*)d_in[22];
  float* out = (float*)d_out;

  float  *p_vars  = (float*)sym(g_vars),   *p_claus = (float*)sym(g_clauses);
  float  *p_stat  = (float*)sym(g_stat);
  __half *p_qh = (__half*)sym(g_qh), *p_ch = (__half*)sym(g_ch), *p_cd = (__half*)sym(g_cd);
  __half *p_cl = (__half*)sym(g_cl), *p_uin = (__half*)sym(g_uin);
  __half *p_uh = (__half*)sym(g_uh), *p_uh2 = (__half*)sym(g_uh2), *p_vraw = (__half*)sym(g_vraw);
  __half *t_q0 = (__half*)sym(g_qW0h), *t_q1 = (__half*)sym(g_qW1h);
  __half *t_c0 = (__half*)sym(g_cW0h), *t_c1 = (__half*)sym(g_cW1h);
  __half *t_u0 = (__half*)sym(g_uW0h), *t_u1 = (__half*)sym(g_uW1h), *t_u2 = (__half*)sym(g_uW2h);
  __half *t_o0 = (__half*)sym(g_oW0h);
  const __half* hnull = nullptr;
  const float*  fnull = nullptr;

  const int T = 256;
  auto B = [](long n){ return (int)((n + 255) / 256); };
  int mbV = (NV + 127) / 128, mbC = (NC + 127) / 128;
  int gbV = (NV + 63) / 64,   gbC = (NC + 63) / 64;

  k_setup0<<<256, T>>>();
  k_count<<<1024, T>>>(lit, vg, cg);
  k_scan<<<1, 1024>>>();
  k_fill<<<1024, T>>>(lit);
  k_wconv<<<256, T>>>(qW0, qW1, cW0, cW1, uW0, uW1, uW2, oW0);

  for(int t = 0; t < ROUNDS; t++){
    const float* nz = noise + (size_t)t * NV * 4;
    k_mma<float,float,64,4,64,1><<<mbV, T>>>(p_vars, nz, 1.f, t_q0, qb0, p_qh, NV, fnull, fnull);
    k_mma<__half,__half,64,0,64,2><<<mbV, T>>>(p_qh, hnull, 0.f, t_q1, qb1, nullptr, NV, fnull, fnull);
    k_cl<<<B((long)NC*8), T>>>(lit);

    k_mma<float,__half,64,64,128,1><<<mbC, T>>>(p_claus, p_cl, 4.f, t_c0, cb0, p_ch, NC, fnull, fnull);
    k_mma<__half,__half,128,0,128,0><<<mbC, T>>>(p_ch, hnull, 0.f, t_c1, cb1, p_cd, NC, fnull, fnull);

    k_zerof<<<B(2L*NG*64), T>>>(p_stat, 2*NG*64);
    k_stats<<<gbC, T>>>(p_cd, 128, 64, cg, NC);
    k_fin<<<8, T>>>(0);
    k_apply<<<B((long)NC*64), T>>>(p_cd, 128, 64, p_claus, cg, NC);

    k_uin<<<(NV+3)/4, T>>>();

    k_mma<__half,__half,256,0,128,1><<<mbV, T>>>(p_uin, hnull, 0.f, t_u0, ub0, p_uh, NV, fnull, fnull);
    k_mma<__half,__half,128,0,128,1><<<mbV, T>>>(p_uh,  hnull, 0.f, t_u1, ub1, p_uh2, NV, fnull, fnull);
    k_mma<__half,__half,128,0,64,0 ><<<mbV, T>>>(p_uh2, hnull, 0.f, t_u2, ub2, p_vraw, NV, fnull, fnull);

    k_zerof<<<B(2L*NG*64), T>>>(p_stat, 2*NG*64);
    k_stats<<<gbV, T>>>(p_vraw, 64, 0, vg, NV);
    k_fin<<<8, T>>>(NG);
    k_apply<<<B((long)NV*64), T>>>(p_vraw, 64, 0, p_vars, vg, NV);
  }

  k_mma<float,float,64,0,64,3><<<mbC, T>>>(p_claus, fnull, 0.f, t_o0, ob0, out, NC, oW1, ob1);

  (void)in_sizes; (void)n_in; (void)out_size;
}

// round 10
// speedup vs baseline: 4.6859x; 1.1862x over previous
#include <cuda_runtime.h>
#include <cuda_fp16.h>
#include <math.h>
#include <stdint.h>

constexpr int NV = 50000, NC = 210000, NE = 630000, NG = 32, ROUNDS = 16;

// ----------------- device scratch -----------------
__device__ float  g_vars   [NV*64];
__device__ float  g_clauses[NC*64];
__device__ __half g_lits   [2*NV*64];
__device__ __half g_sig    [NV*64];
__device__ __half g_cl     [NC*64];
__device__ __half g_cd     [NC*128];
__device__ __half g_uin    [NV*256];
__device__ __half g_vraw   [NV*64];
__device__ int    g_deg    [2*NV];
__device__ int    g_off    [2*NV+1];
__device__ int    g_cur    [2*NV];
__device__ int    g_pcl    [NE];
__device__ float  g_dw     [2*NV];
__device__ float  g_vdw    [NV];
__device__ int    g_gcnt   [2*NG];
__device__ float  g_stat   [2*NG*64];   // zero-init at load; k_fin self-clears
__device__ float  g_mean   [NG*64];
__device__ float  g_rsig   [NG*64];
// fp16 weights, TRANSPOSED [n][k] padded
__device__ __half g_qW0h[64*72];
__device__ __half g_qW1h[64*64];
__device__ __half g_cW0h[128*128];
__device__ __half g_cW1h[128*128];
__device__ __half g_uW0h[128*256];
__device__ __half g_uW1h[128*128];
__device__ __half g_uW2h[64*128];
__device__ __half g_oW0h[64*64];

__device__ __forceinline__ float lrelu(float x){ return x > 0.f ? x : 0.2f*x; }
__device__ __forceinline__ float sp(float x){ return fmaxf(x,0.f) + log1pf(expf(-fabsf(x))); }

__device__ __forceinline__ void mma16(float* c, const uint32_t* a, const uint32_t* b){
  asm("mma.sync.aligned.m16n8k16.row.col.f32.f16.f16.f32 "
      "{%0,%1,%2,%3},{%4,%5,%6,%7},{%8,%9},{%0,%1,%2,%3};"
      : "+f"(c[0]),"+f"(c[1]),"+f"(c[2]),"+f"(c[3])
      : "r"(a[0]),"r"(a[1]),"r"(a[2]),"r"(a[3]),"r"(b[0]),"r"(b[1]));
}
__device__ __forceinline__ void ldmA4(uint32_t* a, uint32_t addr){
  asm volatile("ldmatrix.sync.aligned.m8n8.x4.shared.b16 {%0,%1,%2,%3}, [%4];"
    : "=r"(a[0]),"=r"(a[1]),"=r"(a[2]),"=r"(a[3]) : "r"(addr));
}
__device__ __forceinline__ void ldmB2(uint32_t* b, uint32_t addr){
  asm volatile("ldmatrix.sync.aligned.m8n8.x2.shared.b16 {%0,%1}, [%2];"
    : "=r"(b[0]),"=r"(b[1]) : "r"(addr));
}
__device__ __forceinline__ void load8(const float* A, size_t off, float s, __half2* h){
  float4 v0 = *(const float4*)(A+off), v1 = *(const float4*)(A+off+4);
  h[0]=__floats2half2_rn(v0.x*s, v0.y*s); h[1]=__floats2half2_rn(v0.z*s, v0.w*s);
  h[2]=__floats2half2_rn(v1.x*s, v1.y*s); h[3]=__floats2half2_rn(v1.z*s, v1.w*s);
}
__device__ __forceinline__ void load8(const __half* A, size_t off, float s, __half2* h){
  uint4 u = *(const uint4*)(A+off);
  __half2* p = (__half2*)&u;
  if(s == 1.f){ h[0]=p[0]; h[1]=p[1]; h[2]=p[2]; h[3]=p[3]; }
  else {
    __half2 sc = __float2half2_rn(s);
    h[0]=__hmul2(p[0],sc); h[1]=__hmul2(p[1],sc);
    h[2]=__hmul2(p[2],sc); h[3]=__hmul2(p[3],sc);
  }
}
__device__ __forceinline__ float ldA1(const float* A, size_t i){ return A[i]; }
__device__ __forceinline__ float ldA1(const __half* A, size_t i){ return __half2float(A[i]); }

// ----------------- setup -----------------
__global__ void k_setup0(){
  int i = blockIdx.x*blockDim.x + threadIdx.x, s = gridDim.x*blockDim.x;
  for(int j=i;j<2*NV;j+=s) g_deg[j]=0;
  if(i<2*NG) g_gcnt[i]=0;
}
__global__ void k_count(const int* __restrict__ lit, const int* __restrict__ vg,
                        const int* __restrict__ cg){
  int i = blockIdx.x*blockDim.x + threadIdx.x, s = gridDim.x*blockDim.x;
  for(int j=i;j<NE;j+=s) atomicAdd(&g_deg[lit[j]],1);
  for(int j=i;j<NV;j+=s) atomicAdd(&g_gcnt[NG+vg[j]],1);
  for(int j=i;j<NC;j+=s) atomicAdd(&g_gcnt[cg[j]],1);
}
__global__ void k_scan(){
  __shared__ int sh[1024];
  __shared__ int carry;
  int tid = threadIdx.x;
  if(tid==0) carry=0;
  __syncthreads();
  for(int base=0; base<2*NV; base+=1024){
    int i = base + tid;
    int v = (i < 2*NV) ? g_deg[i] : 0;
    sh[tid] = v; __syncthreads();
    for(int d=1; d<1024; d<<=1){
      int t = (tid>=d) ? sh[tid-d] : 0;
      __syncthreads();
      sh[tid] += t;
      __syncthreads();
    }
    int excl = sh[tid] - v;
    int total = sh[1023];
    int c = carry;
    if(i < 2*NV){ g_off[i] = c + excl; g_cur[i] = c + excl; }
    __syncthreads();
    if(tid==0) carry = c + total;
    __syncthreads();
  }
  if(tid==0) g_off[2*NV] = carry;
  __syncthreads();
  for(int i=tid;i<2*NV;i+=1024) g_dw[i] = rsqrtf(fmaxf((float)g_deg[i],1.f));
  for(int i=tid;i<NV;i+=1024)  g_vdw[i] = 4.f*rsqrtf(fmaxf((float)(g_deg[i]+g_deg[NV+i]),1.f));
}
__global__ void k_fill(const int* __restrict__ lit){
  int i = blockIdx.x*blockDim.x + threadIdx.x, s = gridDim.x*blockDim.x;
  for(int e=i;e<NE;e+=s){
    int l = lit[e];
    int p = atomicAdd(&g_cur[l],1);
    g_pcl[p] = e/3;
  }
  for(int j=i;j<NV*64;j+=s) g_vars[j]=1.f;
  for(int j=i;j<NC*64;j+=s) g_clauses[j]=1.f;
}
__device__ void wtconv(const float* W, __half* WT, int K, int N, int Kp, int i, int s){
  for(int j=i;j<N*Kp;j+=s){
    int n = j/Kp, k = j%Kp;
    WT[j] = __float2half_rn((k < K) ? W[(size_t)k*N + n] : 0.f);
  }
}
__global__ void k_wconv(const float* q0,const float* q1,const float* c0,const float* c1,
                        const float* u0,const float* u1,const float* u2,const float* o0){
  int i = blockIdx.x*blockDim.x + threadIdx.x, s = gridDim.x*blockDim.x;
  wtconv(q0, g_qW0h,  68,  64,  72, i, s);
  wtconv(q1, g_qW1h,  64,  64,  64, i, s);
  wtconv(c0, g_cW0h, 128, 128, 128, i, s);
  wtconv(c1, g_cW1h, 128, 128, 128, i, s);
  wtconv(u0, g_uW0h, 256, 128, 256, i, s);
  wtconv(u1, g_uW1h, 128, 128, 128, i, s);
  wtconv(u2, g_uW2h, 128,  64, 128, i, s);
  wtconv(o0, g_oW0h,  64,  64,  64, i, s);
}

// ----------------- fused multi-layer MLP (fp16 mma, hidden in smem) ----------
// L1: concat(A0,s1*A1)[K0+K1] -> N1 (lrelu, smem)
// L2: N1 -> N2 (if N3>0: lrelu, smem; else final)
// L3: N2 -> N3 (final)            ACT: 0 = store half, 2 = lits epilogue
constexpr int FM_PH  = 72;    // sA/sW pitch (halfs)
constexpr int FM_PHH = 136;   // sH pitch (halfs)
constexpr int FM_SMEM = (128*FM_PH + 128*FM_PH + 128*FM_PHH) * 2;

// one GEMM layer with A already in sH
template<int NIN, int NWo>
__device__ __forceinline__ void gemm_smem(
    float (&acc)[2][NWo][4], const __half* __restrict__ WT, int Nout,
    __half* sW, uint32_t sWb, uint32_t sHb,
    int tid, int lane, int r0, int cb){
  constexpr int KC = 64;
  int lr = lane & 7, bsel = ((lane>>3)&1)*8, asel = ((lane>>4)&1)*8;
  for(int ch=0; ch<NIN/KC; ch++){
    __syncthreads();
    for(int i=tid; i<Nout*(KC/8); i+=256){
      int n = i/(KC/8), kg = i%(KC/8);
      *(uint4*)&sW[n*FM_PH + kg*8] = *(const uint4*)&WT[(size_t)n*NIN + ch*KC + kg*8];
    }
    __syncthreads();
    #pragma unroll
    for(int s=0;s<KC/16;s++){
      int wks = s*16, ks = ch*KC + s*16;
      uint32_t bfr[NWo][2];
      #pragma unroll
      for(int j=0;j<NWo;j++){
        int nrow = cb + j*8 + lr;
        ldmB2(bfr[j], sWb + (uint32_t)(nrow*FM_PH + wks + bsel)*2);
      }
      uint32_t afr[2][4];
      #pragma unroll
      for(int mf=0;mf<2;mf++){
        int row = r0 + mf*16 + lr + ((lane>>3)&1)*8;
        ldmA4(afr[mf], sHb + (uint32_t)(row*FM_PHH + ks + asel)*2);
      }
      #pragma unroll
      for(int mf=0;mf<2;mf++)
        #pragma unroll
        for(int j=0;j<NWo;j++) mma16(acc[mf][j], afr[mf], bfr[j]);
    }
  }
}
template<int NWo>
__device__ __forceinline__ void storeH(float (&acc)[2][NWo][4], __half* sH,
                                       int r0,int cb,int g,int tg){
  #pragma unroll
  for(int mf=0;mf<2;mf++){
    int rr = r0 + mf*16 + g;
    #pragma unroll
    for(int j=0;j<NWo;j++){
      int col = cb + j*8 + 2*tg;
      *(__half2*)&sH[rr*FM_PHH + col]     = __floats2half2_rn(lrelu(acc[mf][j][0]), lrelu(acc[mf][j][1]));
      *(__half2*)&sH[(rr+8)*FM_PHH + col] = __floats2half2_rn(lrelu(acc[mf][j][2]), lrelu(acc[mf][j][3]));
    }
  }
}
template<int NWo>
__device__ __forceinline__ void initB(float (&acc)[2][NWo][4], const float* b, int cb, int tg){
  #pragma unroll
  for(int j=0;j<NWo;j++){
    int col = cb + j*8 + 2*tg;
    float b0v = b[col], b1v = b[col+1];
    #pragma unroll
    for(int mf=0;mf<2;mf++){
      acc[mf][j][0]=b0v; acc[mf][j][1]=b1v; acc[mf][j][2]=b0v; acc[mf][j][3]=b1v;
    }
  }
}

template<typename T0, typename T1, int K0,int K1,int N1,int N2,int N3,int ACT>
__global__ void __launch_bounds__(256) k_fmlp(
    const T0* __restrict__ A0, const T1* __restrict__ A1, float s1,
    const __half* __restrict__ WT0, const float* __restrict__ b0,
    const __half* __restrict__ WT1, const float* __restrict__ b1,
    const __half* __restrict__ WT2, const float* __restrict__ b2,
    void* Cv, int M){
  constexpr int K  = K0 + K1;
  constexpr int Kp = (K + 7) & ~7;
  constexpr int KC = 64;
  constexpr int CW = 2, RW = 4;
  constexpr int NW1 = N1/8/CW;
  constexpr int NF  = (N3>0) ? N3 : N2;
  constexpr int NWF = NF/8/CW;
  extern __shared__ __align__(16) __half smem[];
  __half* sA = smem;                 // 128*72
  __half* sW = sA + 128*FM_PH;       // 128*72
  __half* sH = sW + 128*FM_PH;       // 128*136
  int tid = threadIdx.x;
  int w = tid >> 5, lane = tid & 31;
  int g = lane >> 2, tg = lane & 3;
  int wr = w % RW, wc = w / RW;
  int base = blockIdx.x * 128;
  int r0 = wr * 32;
  uint32_t sAb = (uint32_t)__cvta_generic_to_shared(sA);
  uint32_t sWb = (uint32_t)__cvta_generic_to_shared(sW);
  uint32_t sHb = (uint32_t)__cvta_generic_to_shared(sH);
  int lr = lane & 7, bsel = ((lane>>3)&1)*8, asel = ((lane>>4)&1)*8;

  // ---- Layer 1 (A from global) ----
  int cb1 = wc * NW1 * 8;
  float acc1[2][NW1][4];
  initB(acc1, b0, cb1, tg);
  constexpr int NCH1 = (K + KC - 1)/KC;
  for(int ch=0; ch<NCH1; ch++){
    int k0c = ch*KC;
    __syncthreads();
    for(int i=tid; i<N1*(KC/8); i+=256){
      int n = i/(KC/8), kg = i%(KC/8);
      int col0 = k0c + kg*8;
      uint4 u = make_uint4(0u,0u,0u,0u);
      if(col0 + 8 <= Kp) u = *(const uint4*)&WT0[(size_t)n*Kp + col0];
      *(uint4*)&sW[n*FM_PH + kg*8] = u;
    }
    for(int i=tid; i<128*(KC/8); i+=256){
      int r = i/(KC/8), kg = i%(KC/8);
      int col0 = k0c + kg*8;
      int row = base + r;
      __half2 h[4];
      h[0]=h[1]=h[2]=h[3]=__float2half2_rn(0.f);
      if(row < M){
        if(col0 + 8 <= K0) load8(A0, (size_t)row*K0 + col0, 1.f, h);
        else if(col0 >= K0 && col0 + 8 <= K0+K1) load8(A1, (size_t)row*K1 + (col0-K0), s1, h);
        else if(col0 < K0+K1){
          float t[8];
          #pragma unroll
          for(int e=0;e<8;e++){
            int c = col0 + e; float x = 0.f;
            if(c < K0) x = ldA1(A0, (size_t)row*K0 + c);
            else if(c < K0+K1) x = s1 * ldA1(A1, (size_t)row*K1 + (c-K0));
            t[e] = x;
          }
          h[0]=__floats2half2_rn(t[0],t[1]); h[1]=__floats2half2_rn(t[2],t[3]);
          h[2]=__floats2half2_rn(t[4],t[5]); h[3]=__floats2half2_rn(t[6],t[7]);
        }
      }
      *(uint4*)&sA[r*FM_PH + kg*8] = *(uint4*)h;
    }
    __syncthreads();
    #pragma unroll
    for(int s=0;s<KC/16;s++){
      int ks = s*16;
      uint32_t bfr[NW1][2];
      #pragma unroll
      for(int j=0;j<NW1;j++){
        int nrow = cb1 + j*8 + lr;
        ldmB2(bfr[j], sWb + (uint32_t)(nrow*FM_PH + ks + bsel)*2);
      }
      uint32_t afr[2][4];
      #pragma unroll
      for(int mf=0;mf<2;mf++){
        int row = r0 + mf*16 + lr + ((lane>>3)&1)*8;
        ldmA4(afr[mf], sAb + (uint32_t)(row*FM_PH + ks + asel)*2);
      }
      #pragma unroll
      for(int mf=0;mf<2;mf++)
        #pragma unroll
        for(int j=0;j<NW1;j++) mma16(acc1[mf][j], afr[mf], bfr[j]);
    }
  }
  storeH(acc1, sH, r0, cb1, g, tg);   // visibility via first sync of next layer

  // ---- Layer 2 (+3) ----
  float facc[2][NWF][4];
  int cbF = wc * NWF * 8;
  if constexpr (N3 == 0){
    initB(facc, b1, cbF, tg);
    gemm_smem<N1,NWF>(facc, WT1, N2, sW, sWb, sHb, tid, lane, r0, cbF);
  } else {
    constexpr int NW2 = N2/8/CW;
    int cb2 = wc * NW2 * 8;
    float acc2[2][NW2][4];
    initB(acc2, b1, cb2, tg);
    gemm_smem<N1,NW2>(acc2, WT1, N2, sW, sWb, sHb, tid, lane, r0, cb2);
    __syncthreads();                   // all reads of sH complete
    storeH(acc2, sH, r0, cb2, g, tg);
    initB(facc, b2, cbF, tg);
    gemm_smem<N2,NWF>(facc, WT2, N3, sW, sWb, sHb, tid, lane, r0, cbF);
  }

  // ---- epilogue ----
  if constexpr (ACT == 0){
    __half* C = (__half*)Cv;
    #pragma unroll
    for(int mf=0;mf<2;mf++){
      int row0 = base + r0 + mf*16 + g;
      int row1 = row0 + 8;
      #pragma unroll
      for(int j=0;j<NWF;j++){
        int col = cbF + j*8 + 2*tg;
        if(row0 < M) *(__half2*)&C[(size_t)row0*NF + col] = __floats2half2_rn(facc[mf][j][0], facc[mf][j][1]);
        if(row1 < M) *(__half2*)&C[(size_t)row1*NF + col] = __floats2half2_rn(facc[mf][j][2], facc[mf][j][3]);
      }
    }
  } else { // ACT==2: lits epilogue (NF==64)
    #pragma unroll
    for(int mf=0;mf<2;mf++){
      #pragma unroll
      for(int j=0;j<NWF;j++){
        int col = cbF + j*8 + 2*tg;
        #pragma unroll
        for(int h=0;h<2;h++){
          int row = base + r0 + mf*16 + g + 8*h;
          if(row < M){
            float qa = facc[mf][j][2*h], qb = facc[mf][j][2*h+1];
            *(__half2*)&g_lits[(size_t)row*64 + col]      = __floats2half2_rn(sp(qa), sp(qb));
            *(__half2*)&g_lits[(size_t)(NV+row)*64 + col] = __floats2half2_rn(sp(-qa), sp(-qb));
            *(__half2*)&g_sig [(size_t)row*64 + col]      =
                __floats2half2_rn(1.f/(1.f+expf(-qa)), 1.f/(1.f+expf(-qb)));
          }
        }
      }
    }
  }
}

// ----------------- head kernel (unchanged from R9, static smem) -------------
__global__ void __launch_bounds__(256) k_head(
    const float* __restrict__ A0, const __half* __restrict__ WT,
    const float* __restrict__ b, float* __restrict__ C, int M,
    const float* __restrict__ w2, const float* __restrict__ b2){
  constexpr int K = 64, Kp = 64, KC = 64, PH = 72, N = 64;
  constexpr int RW = 8, MF = 1, NW = 8;
  __shared__ __align__(16) __half sA[128*PH];
  __shared__ __align__(16) __half sW[N*PH];
  int tid = threadIdx.x;
  int w = tid >> 5, lane = tid & 31;
  int g = lane >> 2, tg = lane & 3;
  int base = blockIdx.x * 128;
  int r0 = w * 16;
  float acc[NW][4];
  #pragma unroll
  for(int j=0;j<NW;j++){
    int col = j*8 + 2*tg;
    float b0v = b[col], b1v = b[col+1];
    acc[j][0]=b0v; acc[j][1]=b1v; acc[j][2]=b0v; acc[j][3]=b1v;
  }
  uint32_t sAb = (uint32_t)__cvta_generic_to_shared(sA);
  uint32_t sWb = (uint32_t)__cvta_generic_to_shared(sW);
  for(int i=tid; i<N*(KC/8); i+=256){
    int n = i/(KC/8), kg = i%(KC/8);
    *(uint4*)&sW[n*PH + kg*8] = *(const uint4*)&WT[(size_t)n*Kp + kg*8];
  }
  for(int i=tid; i<128*(KC/8); i+=256){
    int r = i/(KC/8), kg = i%(KC/8);
    int row = base + r;
    __half2 h[4];
    h[0]=h[1]=h[2]=h[3]=__float2half2_rn(0.f);
    if(row < M) load8(A0, (size_t)row*K + kg*8, 1.f, h);
    *(uint4*)&sA[r*PH + kg*8] = *(uint4*)h;
  }
  __syncthreads();
  int lr = lane & 7;
  #pragma unroll
  for(int s=0;s<KC/16;s++){
    int ks = s*16;
    uint32_t bfr[NW][2];
    #pragma unroll
    for(int j=0;j<NW;j++){
      int nrow = j*8 + lr;
      ldmB2(bfr[j], sWb + (uint32_t)(nrow*PH + ks + ((lane>>3)&1)*8)*2);
    }
    uint32_t afr[4];
    {
      int row = r0 + lr + ((lane>>3)&1)*8;
      ldmA4(afr, sAb + (uint32_t)(row*PH + ks + ((lane>>4)&1)*8)*2);
    }
    #pragma unroll
    for(int j=0;j<NW;j++) mma16(acc[j], afr, bfr[j]);
  }
  float p0 = 0.f, p1 = 0.f;
  #pragma unroll
  for(int j=0;j<NW;j++){
    int col = j*8 + 2*tg;
    float wa = w2[col], wb = w2[col+1];
    p0 += lrelu(acc[j][0])*wa + lrelu(acc[j][1])*wb;
    p1 += lrelu(acc[j][2])*wa + lrelu(acc[j][3])*wb;
  }
  #pragma unroll
  for(int o=2;o>0;o>>=1){
    p0 += __shfl_down_sync(0xffffffffu, p0, o, 4);
    p1 += __shfl_down_sync(0xffffffffu, p1, o, 4);
  }
  if(tg == 0){
    int row0 = base + r0 + g;
    int row1 = row0 + 8;
    float bb = b2[0];
    if(row0 < M){
      float lg = p0 + bb;
      C[row0] = 1.f/(1.f+expf(-lg)); C[NC + row0] = sp(lg);
    }
    if(row1 < M){
      float lg = p1 + bb;
      C[row1] = 1.f/(1.f+expf(-lg)); C[NC + row1] = sp(lg);
    }
  }
}

// ----------------- per-round graph kernels -----------------
__global__ void k_cl(const int* __restrict__ lit){
  int idx = blockIdx.x*blockDim.x + threadIdx.x;
  if(idx >= NC*8) return;
  int c = idx >> 3, q = (idx & 7) * 8;
  int e = 3*c;
  int l0 = lit[e], l1 = lit[e+1], l2 = lit[e+2];
  uint4 ua = *(const uint4*)&g_lits[(size_t)l0*64 + q];
  uint4 ub = *(const uint4*)&g_lits[(size_t)l1*64 + q];
  uint4 uc = *(const uint4*)&g_lits[(size_t)l2*64 + q];
  __half2* pa = (__half2*)&ua; __half2* pb = (__half2*)&ub; __half2* pc = (__half2*)&uc;
  __half2 o[4];
  #pragma unroll
  for(int p=0;p<4;p++){
    float2 fa = __half22float2(pa[p]), fb = __half22float2(pb[p]), fc = __half22float2(pc[p]);
    o[p] = __floats2half2_rn(expf(-(fa.x+fb.x+fc.x)), expf(-(fa.y+fb.y+fc.y)));
  }
  *(uint4*)&g_cl[(size_t)c*64 + q] = *(uint4*)o;
}

__global__ void __launch_bounds__(256) k_uin(){
  int tid = threadIdx.x;
  int f = tid & 63;
  int v = blockIdx.x*4 + (tid >> 6);
  if(v >= NV) return;
  int p0 = g_off[v],    p1 = g_off[v+1];
  int n0 = g_off[NV+v], n1 = g_off[NV+v+1];
  float scl=0.f, scd=0.f, ncl=0.f, ncd=0.f;
  for(int e=p0;e<p1;e++){
    int c = g_pcl[e];
    scl += __half2float(g_cl[(size_t)c*64 + f]);
    scd += __half2float(g_cd[(size_t)c*128 + f]);
  }
  for(int e=n0;e<n1;e++){
    int c = g_pcl[e];
    ncl += __half2float(g_cl[(size_t)c*64 + f]);
    ncd += __half2float(g_cd[(size_t)c*128 + f]);
  }
  float sg = __half2float(g_sig[(size_t)v*64 + f]);
  float gr = (-sg*scl + (1.f-sg)*ncl) * g_vdw[v];
  size_t o = (size_t)v*256;
  g_uin[o + f]       = __float2half_rn(gr);
  g_uin[o + 64 + f]  = __float2half_rn(g_vars[(size_t)v*64 + f]);
  g_uin[o + 128 + f] = __float2half_rn(scd * g_dw[v]);
  g_uin[o + 192 + f] = __float2half_rn(ncd * g_dw[NV+v]);
}

// ----------------- pair-norm -----------------
__global__ void k_stats(const __half* __restrict__ src, int S, int off,
                        const int* __restrict__ gid, int n){
  __shared__ float s1[256], s2[256];
  int tid = threadIdx.x;
  int f = tid & 63, lane = tid >> 6;
  int row0 = blockIdx.x * 64;
  int rend = min(row0 + 64, n);
  int g0 = gid[row0], g1 = gid[rend-1];
  if(g0 == g1){
    float s = 0.f, q = 0.f;
    for(int r = row0 + lane; r < rend; r += 4){
      float x = __half2float(src[(size_t)r*S + off + f]);
      s += x; q += x*x;
    }
    s1[tid] = s; s2[tid] = q;
    __syncthreads();
    if(lane == 0){
      s = s1[f] + s1[64+f] + s1[128+f] + s1[192+f];
      q = s2[f] + s2[64+f] + s2[128+f] + s2[192+f];
      atomicAdd(&g_stat[g0*64 + f], s);
      atomicAdd(&g_stat[NG*64 + g0*64 + f], q);
    }
  } else {
    for(int r = row0 + lane; r < rend; r += 4){
      float x = __half2float(src[(size_t)r*S + off + f]);
      int g = gid[r];
      atomicAdd(&g_stat[g*64 + f], x);
      atomicAdd(&g_stat[NG*64 + g*64 + f], x*x);
    }
  }
}
__global__ void k_fin(int cntoff){
  int i = blockIdx.x*blockDim.x + threadIdx.x;
  if(i >= NG*64) return;
  int g = i >> 6;
  float inv = 1.f / fmaxf((float)g_gcnt[cntoff + g], 1.f);
  float m = g_stat[i] * inv;
  float var = g_stat[NG*64 + i] * inv - m*m;
  g_mean[i] = m;
  g_rsig[i] = rsqrtf(fmaxf(var, 0.f) + 1e-6f);
  g_stat[i] = 0.f;            // self-clear for next use / next launch
  g_stat[NG*64 + i] = 0.f;
}
__global__ void k_apply(const __half* __restrict__ src, int S, int off,
                        float* __restrict__ target, const int* __restrict__ gid, int n){
  int i = blockIdx.x*blockDim.x + threadIdx.x;
  if(i >= n*64) return;
  int r = i >> 6, f = i & 63;
  int g = gid[r];
  float x = __half2float(src[(size_t)r*S + off + f]);
  float y = (x - g_mean[g*64+f]) * g_rsig[g*64+f] * 0.25f;
  target[i] = y + 0.1f * target[i];
}

// ----------------- host -----------------
static void* sym(const void* s){ void* p=nullptr; cudaGetSymbolAddress(&p, s); return p; }

extern "C" void kernel_launch(void* const* d_in, const int* in_sizes, int n_in,
                              void* d_out, int out_size){
  const int*   lit   = (const int*)d_in[0];
  const int*   vg    = (const int*)d_in[2];
  const int*   cg    = (const int*)d_in[3];
  const float* noise = (const float*)d_in[4];
  const float *qW0=(const float*)d_in[5],  *qb0=(const float*)d_in[6];
  const float *qW1=(const float*)d_in[7],  *qb1=(const float*)d_in[8];
  const float *cW0=(const float*)d_in[9],  *cb0=(const float*)d_in[10];
  const float *cW1=(const float*)d_in[11], *cb1=(const float*)d_in[12];
  const float *uW0=(const float*)d_in[13], *ub0=(const float*)d_in[14];
  const float *uW1=(const float*)d_in[15], *ub1=(const float*)d_in[16];
  const float *uW2=(const float*)d_in[17], *ub2=(const float*)d_in[18];
  const float *oW0=(const float*)d_in[19], *ob0=(const float*)d_in[20];
  const float *oW1=(const float*)d_in[21], *ob1=(const float*)d_in[22];
  float* out = (float*)d_out;

  float  *p_vars  = (float*)sym(g_vars),   *p_claus = (float*)sym(g_clauses);
  __half *p_cd = (__half*)sym(g_cd), *p_cl = (__half*)sym(g_cl);
  __half *p_uin = (__half*)sym(g_uin), *p_vraw = (__half*)sym(g_vraw);
  __half *t_q0 = (__half*)sym(g_qW0h), *t_q1 = (__half*)sym(g_qW1h);
  __half *t_c0 = (__half*)sym(g_cW0h), *t_c1 = (__half*)sym(g_cW1h);
  __half *t_u0 = (__half*)sym(g_uW0h), *t_u1 = (__half*)sym(g_uW1h), *t_u2 = (__half*)sym(g_uW2h);
  __half *t_o0 = (__half*)sym(g_oW0h);
  const __half* hnull = nullptr;

  auto fq = k_fmlp<float,float,64,4,64,64,0,2>;
  auto fc = k_fmlp<float,__half,64,64,128,128,0,0>;
  auto fu = k_fmlp<__half,__half,256,0,128,128,64,0>;
  cudaFuncSetAttribute(fq, cudaFuncAttributeMaxDynamicSharedMemorySize, FM_SMEM);
  cudaFuncSetAttribute(fc, cudaFuncAttributeMaxDynamicSharedMemorySize, FM_SMEM);
  cudaFuncSetAttribute(fu, cudaFuncAttributeMaxDynamicSharedMemorySize, FM_SMEM);

  const int T = 256;
  auto B = [](long n){ return (int)((n + 255) / 256); };
  int mbV = (NV + 127) / 128, mbC = (NC + 127) / 128;
  int gbV = (NV + 63) / 64,   gbC = (NC + 63) / 64;

  k_setup0<<<256, T>>>();
  k_count<<<1024, T>>>(lit, vg, cg);
  k_scan<<<1, 1024>>>();
  k_fill<<<1024, T>>>(lit);
  k_wconv<<<256, T>>>(qW0, qW1, cW0, cW1, uW0, uW1, uW2, oW0);

  for(int t = 0; t < ROUNDS; t++){
    const float* nz = noise + (size_t)t * NV * 4;
    fq<<<mbV, T, FM_SMEM>>>(p_vars, nz, 1.f, t_q0, qb0, t_q1, qb1, hnull, nullptr, nullptr, NV);
    k_cl<<<B((long)NC*8), T>>>(lit);

    fc<<<mbC, T, FM_SMEM>>>(p_claus, p_cl, 4.f, t_c0, cb0, t_c1, cb1, hnull, nullptr, p_cd, NC);

    k_stats<<<gbC, T>>>(p_cd, 128, 64, cg, NC);
    k_fin<<<8, T>>>(0);
    k_apply<<<B((long)NC*64), T>>>(p_cd, 128, 64, p_claus, cg, NC);

    k_uin<<<(NV+3)/4, T>>>();

    fu<<<mbV, T, FM_SMEM>>>(p_uin, hnull, 0.f, t_u0, ub0, t_u1, ub1, t_u2, ub2, p_vraw, NV);

    k_stats<<<gbV, T>>>(p_vraw, 64, 0, vg, NV);
    k_fin<<<8, T>>>(NG);
    k_apply<<<B((long)NV*64), T>>>(p_vraw, 64, 0, p_vars, vg, NV);
  }

  k_head<<<mbC, T>>>(p_claus, t_o0, ob0, out, NC, oW1, ob1);

  (void)in_sizes; (void)n_in; (void)out_size;
}

// round 12
// speedup vs baseline: 4.9638x; 1.0593x over previous
#include <cuda_runtime.h>
#include <cuda_fp16.h>
#include <math.h>
#include <stdint.h>

constexpr int NV = 50000, NC = 210000, NE = 630000, NG = 32, ROUNDS = 16;

// ----------------- device scratch -----------------
__device__ float  g_vars   [NV*64];
__device__ float  g_clauses[NC*64];
__device__ __half g_lits   [2*NV*64];
__device__ __half g_sig    [NV*64];
__device__ __half g_cl     [NC*64];
__device__ __half g_cd     [NC*128];
__device__ __half g_uin    [NV*256];
__device__ __half g_vraw   [NV*64];
__device__ int    g_deg    [2*NV];
__device__ int    g_off    [2*NV+1];
__device__ int    g_cur    [2*NV];
__device__ int    g_pcl    [NE];
__device__ float  g_dw     [2*NV];
__device__ float  g_vdw    [NV];
__device__ int    g_gcnt   [2*NG];
__device__ float  g_statC  [2*NG*64];   // zero-init; k_fin2 self-clears
__device__ float  g_statV  [2*NG*64];
__device__ float  g_meanC  [NG*64];
__device__ float  g_rsigC  [NG*64];
__device__ float  g_meanV  [NG*64];
__device__ float  g_rsigV  [NG*64];
// fp16 weights, TRANSPOSED [n][k] padded
__device__ __half g_qW0h[64*72];
__device__ __half g_qW1h[64*64];
__device__ __half g_cW0h[128*128];
__device__ __half g_cW1h[128*128];
__device__ __half g_uW0h[128*256];
__device__ __half g_uW1h[128*128];
__device__ __half g_uW2h[64*128];
__device__ __half g_oW0h[64*64];

__device__ __forceinline__ float lrelu(float x){ return x > 0.f ? x : 0.2f*x; }
__device__ __forceinline__ float sp(float x){ return fmaxf(x,0.f) + log1pf(expf(-fabsf(x))); }

__device__ __forceinline__ void mma16(float* c, const uint32_t* a, const uint32_t* b){
  asm("mma.sync.aligned.m16n8k16.row.col.f32.f16.f16.f32 "
      "{%0,%1,%2,%3},{%4,%5,%6,%7},{%8,%9},{%0,%1,%2,%3};"
      : "+f"(c[0]),"+f"(c[1]),"+f"(c[2]),"+f"(c[3])
      : "r"(a[0]),"r"(a[1]),"r"(a[2]),"r"(a[3]),"r"(b[0]),"r"(b[1]));
}
__device__ __forceinline__ void ldmA4(uint32_t* a, uint32_t addr){
  asm volatile("ldmatrix.sync.aligned.m8n8.x4.shared.b16 {%0,%1,%2,%3}, [%4];"
    : "=r"(a[0]),"=r"(a[1]),"=r"(a[2]),"=r"(a[3]) : "r"(addr));
}
__device__ __forceinline__ void ldmB2(uint32_t* b, uint32_t addr){
  asm volatile("ldmatrix.sync.aligned.m8n8.x2.shared.b16 {%0,%1}, [%2];"
    : "=r"(b[0]),"=r"(b[1]) : "r"(addr));
}
__device__ __forceinline__ void load8(const float* A, size_t off, float s, __half2* h){
  float4 v0 = *(const float4*)(A+off), v1 = *(const float4*)(A+off+4);
  h[0]=__floats2half2_rn(v0.x*s, v0.y*s); h[1]=__floats2half2_rn(v0.z*s, v0.w*s);
  h[2]=__floats2half2_rn(v1.x*s, v1.y*s); h[3]=__floats2half2_rn(v1.z*s, v1.w*s);
}
__device__ __forceinline__ void load8(const __half* A, size_t off, float s, __half2* h){
  uint4 u = *(const uint4*)(A+off);
  __half2* p = (__half2*)&u;
  if(s == 1.f){ h[0]=p[0]; h[1]=p[1]; h[2]=p[2]; h[3]=p[3]; }
  else {
    __half2 sc = __float2half2_rn(s);
    h[0]=__hmul2(p[0],sc); h[1]=__hmul2(p[1],sc);
    h[2]=__hmul2(p[2],sc); h[3]=__hmul2(p[3],sc);
  }
}
__device__ __forceinline__ float ldA1(const float* A, size_t i){ return A[i]; }
__device__ __forceinline__ float ldA1(const __half* A, size_t i){ return __half2float(A[i]); }

// fused pair-norm apply for 8 state cols: new = (prev-mean)*rsig*0.25 + 0.1*state
__device__ __forceinline__ void apply8(float* state, const __half* prev,
    int pstride, int poff, const float* mean, const float* rsig,
    int gg, int row, int col0, int first, __half2* h){
  float nv[8];
  if(first){
    #pragma unroll
    for(int e=0;e<8;e++) nv[e]=1.f;
  } else {
    uint4 pu = *(const uint4*)&prev[(size_t)row*pstride + poff + col0];
    __half2* ph = (__half2*)&pu;
    const float* mb = &mean[gg*64 + col0];
    const float* rb = &rsig[gg*64 + col0];
    const float* sb = &state[(size_t)row*64 + col0];
    float4 m0=*(const float4*)mb, m1=*(const float4*)(mb+4);
    float4 r0=*(const float4*)rb, r1=*(const float4*)(rb+4);
    float4 s0=*(const float4*)sb, s1=*(const float4*)(sb+4);
    float2 p0=__half22float2(ph[0]), p1=__half22float2(ph[1]);
    float2 p2=__half22float2(ph[2]), p3=__half22float2(ph[3]);
    nv[0]=(p0.x-m0.x)*r0.x*0.25f + 0.1f*s0.x;
    nv[1]=(p0.y-m0.y)*r0.y*0.25f + 0.1f*s0.y;
    nv[2]=(p1.x-m0.z)*r0.z*0.25f + 0.1f*s0.z;
    nv[3]=(p1.y-m0.w)*r0.w*0.25f + 0.1f*s0.w;
    nv[4]=(p2.x-m1.x)*r1.x*0.25f + 0.1f*s1.x;
    nv[5]=(p2.y-m1.y)*r1.y*0.25f + 0.1f*s1.y;
    nv[6]=(p3.x-m1.z)*r1.z*0.25f + 0.1f*s1.z;
    nv[7]=(p3.y-m1.w)*r1.w*0.25f + 0.1f*s1.w;
  }
  float* sw = &state[(size_t)row*64 + col0];
  *(float4*)sw     = make_float4(nv[0],nv[1],nv[2],nv[3]);
  *(float4*)(sw+4) = make_float4(nv[4],nv[5],nv[6],nv[7]);
  h[0]=__floats2half2_rn(nv[0],nv[1]); h[1]=__floats2half2_rn(nv[2],nv[3]);
  h[2]=__floats2half2_rn(nv[4],nv[5]); h[3]=__floats2half2_rn(nv[6],nv[7]);
}

// ----------------- setup -----------------
__global__ void k_count(const int* __restrict__ lit, const int* __restrict__ vg,
                        const int* __restrict__ cg){
  int i = blockIdx.x*blockDim.x + threadIdx.x, s = gridDim.x*blockDim.x;
  for(int j=i;j<NE;j+=s) atomicAdd(&g_deg[lit[j]],1);
  for(int j=i;j<NV;j+=s) atomicAdd(&g_gcnt[NG+vg[j]],1);
  for(int j=i;j<NC;j+=s) atomicAdd(&g_gcnt[cg[j]],1);
}
__global__ void k_scan(){
  __shared__ int sh[1024];
  __shared__ int carry;
  int tid = threadIdx.x;
  if(tid==0) carry=0;
  __syncthreads();
  for(int base=0; base<2*NV; base+=1024){
    int i = base + tid;
    int v = (i < 2*NV) ? g_deg[i] : 0;
    sh[tid] = v; __syncthreads();
    for(int d=1; d<1024; d<<=1){
      int t = (tid>=d) ? sh[tid-d] : 0;
      __syncthreads();
      sh[tid] += t;
      __syncthreads();
    }
    int excl = sh[tid] - v;
    int total = sh[1023];
    int c = carry;
    if(i < 2*NV){ g_off[i] = c + excl; g_cur[i] = c + excl; }
    __syncthreads();
    if(tid==0) carry = c + total;
    __syncthreads();
  }
  if(tid==0) g_off[2*NV] = carry;
  __syncthreads();
  for(int i=tid;i<2*NV;i+=1024) g_dw[i] = rsqrtf(fmaxf((float)g_deg[i],1.f));
  for(int i=tid;i<NV;i+=1024)  g_vdw[i] = 4.f*rsqrtf(fmaxf((float)(g_deg[i]+g_deg[NV+i]),1.f));
  __syncthreads();
  for(int i=tid;i<2*NV;i+=1024) g_deg[i] = 0;   // clean for next graph replay
}
__device__ void wtconv(const float* W, __half* WT, int K, int N, int Kp, int i, int s){
  for(int j=i;j<N*Kp;j+=s){
    int n = j/Kp, k = j%Kp;
    WT[j] = __float2half_rn((k < K) ? W[(size_t)k*N + n] : 0.f);
  }
}
__global__ void k_fillw(const int* __restrict__ lit,
                        const float* q0,const float* q1,const float* c0,const float* c1,
                        const float* u0,const float* u1,const float* u2,const float* o0){
  int i = blockIdx.x*blockDim.x + threadIdx.x, s = gridDim.x*blockDim.x;
  for(int e=i;e<NE;e+=s){
    int l = lit[e];
    int p = atomicAdd(&g_cur[l],1);
    g_pcl[p] = e/3;
  }
  wtconv(q0, g_qW0h,  68,  64,  72, i, s);
  wtconv(q1, g_qW1h,  64,  64,  64, i, s);
  wtconv(c0, g_cW0h, 128, 128, 128, i, s);
  wtconv(c1, g_cW1h, 128, 128, 128, i, s);
  wtconv(u0, g_uW0h, 256, 128, 256, i, s);
  wtconv(u1, g_uW1h, 128, 128, 128, i, s);
  wtconv(u2, g_uW2h, 128,  64, 128, i, s);
  wtconv(o0, g_oW0h,  64,  64,  64, i, s);
}

// ----------------- fused multi-layer MLP -----------------
constexpr int FM_PH  = 72;
constexpr int FM_PHH = 136;
constexpr int FM_SMEM = (128*FM_PH + 128*FM_PH + 128*FM_PHH) * 2;

template<int NIN, int NWo>
__device__ __forceinline__ void gemm_smem(
    float (&acc)[2][NWo][4], const __half* __restrict__ WT, int Nout,
    __half* sW, uint32_t sWb, uint32_t sHb,
    int tid, int lane, int r0, int cb){
  constexpr int KC = 64;
  int lr = lane & 7, bsel = ((lane>>3)&1)*8, asel = ((lane>>4)&1)*8;
  for(int ch=0; ch<NIN/KC; ch++){
    __syncthreads();
    for(int i=tid; i<Nout*(KC/8); i+=256){
      int n = i/(KC/8), kg = i%(KC/8);
      *(uint4*)&sW[n*FM_PH + kg*8] = *(const uint4*)&WT[(size_t)n*NIN + ch*KC + kg*8];
    }
    __syncthreads();
    #pragma unroll
    for(int s=0;s<KC/16;s++){
      int wks = s*16, ks = ch*KC + s*16;
      uint32_t bfr[NWo][2];
      #pragma unroll
      for(int j=0;j<NWo;j++){
        int nrow = cb + j*8 + lr;
        ldmB2(bfr[j], sWb + (uint32_t)(nrow*FM_PH + wks + bsel)*2);
      }
      uint32_t afr[2][4];
      #pragma unroll
      for(int mf=0;mf<2;mf++){
        int row = r0 + mf*16 + lr + ((lane>>3)&1)*8;
        ldmA4(afr[mf], sHb + (uint32_t)(row*FM_PHH + ks + asel)*2);
      }
      #pragma unroll
      for(int mf=0;mf<2;mf++)
        #pragma unroll
        for(int j=0;j<NWo;j++) mma16(acc[mf][j], afr[mf], bfr[j]);
    }
  }
}
template<int NWo>
__device__ __forceinline__ void storeH(float (&acc)[2][NWo][4], __half* sH,
                                       int r0,int cb,int g,int tg){
  #pragma unroll
  for(int mf=0;mf<2;mf++){
    int rr = r0 + mf*16 + g;
    #pragma unroll
    for(int j=0;j<NWo;j++){
      int col = cb + j*8 + 2*tg;
      *(__half2*)&sH[rr*FM_PHH + col]     = __floats2half2_rn(lrelu(acc[mf][j][0]), lrelu(acc[mf][j][1]));
      *(__half2*)&sH[(rr+8)*FM_PHH + col] = __floats2half2_rn(lrelu(acc[mf][j][2]), lrelu(acc[mf][j][3]));
    }
  }
}
template<int NWo>
__device__ __forceinline__ void initB(float (&acc)[2][NWo][4], const float* b, int cb, int tg){
  #pragma unroll
  for(int j=0;j<NWo;j++){
    int col = cb + j*8 + 2*tg;
    float b0v = b[col], b1v = b[col+1];
    #pragma unroll
    for(int mf=0;mf<2;mf++){
      acc[mf][j][0]=b0v; acc[mf][j][1]=b1v; acc[mf][j][2]=b0v; acc[mf][j][3]=b1v;
    }
  }
}

// FAPP: 1 = layer-1 A0 is fp32 state with fused pair-norm apply (+writeback)
// STATS: 1 = accumulate sum/sumsq of final output cols [NF-64, NF) into statbuf
template<typename T0, typename T1, int K0,int K1,int N1,int N2,int N3,int ACT,int FAPP,int STATS>
__global__ void __launch_bounds__(256) k_fmlp(
    T0* __restrict__ A0, const T1* __restrict__ A1, float s1,
    const __half* __restrict__ prev, int pstride, int poff,
    const float* __restrict__ pmean, const float* __restrict__ prsig,
    const int* __restrict__ gid, int first,
    const __half* __restrict__ WT0, const float* __restrict__ b0,
    const __half* __restrict__ WT1, const float* __restrict__ b1,
    const __half* __restrict__ WT2, const float* __restrict__ b2,
    void* Cv, int M, float* __restrict__ statbuf){
  constexpr int K  = K0 + K1;
  constexpr int Kp = (K + 7) & ~7;
  constexpr int KC = 64;
  constexpr int CW = 2, RW = 4;
  constexpr int NW1 = N1/8/CW;
  constexpr int NF  = (N3>0) ? N3 : N2;
  constexpr int NWF = NF/8/CW;
  extern __shared__ __align__(16) __half smem[];
  __half* sA = smem;
  __half* sW = sA + 128*FM_PH;
  __half* sH = sW + 128*FM_PH;
  int tid = threadIdx.x;
  int w = tid >> 5, lane = tid & 31;
  int g = lane >> 2, tg = lane & 3;
  int wr = w % RW, wc = w / RW;
  int base = blockIdx.x * 128;
  int r0 = wr * 32;
  uint32_t sAb = (uint32_t)__cvta_generic_to_shared(sA);
  uint32_t sWb = (uint32_t)__cvta_generic_to_shared(sW);
  uint32_t sHb = (uint32_t)__cvta_generic_to_shared(sH);
  int lr = lane & 7, bsel = ((lane>>3)&1)*8, asel = ((lane>>4)&1)*8;

  // ---- Layer 1 (A from global; optional fused apply) ----
  int cb1 = wc * NW1 * 8;
  float acc1[2][NW1][4];
  initB(acc1, b0, cb1, tg);
  constexpr int NCH1 = (K + KC - 1)/KC;
  for(int ch=0; ch<NCH1; ch++){
    int k0c = ch*KC;
    __syncthreads();
    for(int i=tid; i<N1*(KC/8); i+=256){
      int n = i/(KC/8), kg = i%(KC/8);
      int col0 = k0c + kg*8;
      uint4 u = make_uint4(0u,0u,0u,0u);
      if(col0 + 8 <= Kp) u = *(const uint4*)&WT0[(size_t)n*Kp + col0];
      *(uint4*)&sW[n*FM_PH + kg*8] = u;
    }
    for(int i=tid; i<128*(KC/8); i+=256){
      int r = i/(KC/8), kg = i%(KC/8);
      int col0 = k0c + kg*8;
      int row = base + r;
      __half2 h[4];
      h[0]=h[1]=h[2]=h[3]=__float2half2_rn(0.f);
      if(row < M){
        if(col0 + 8 <= K0){
          if constexpr (FAPP){
            apply8((float*)A0, prev, pstride, poff, pmean, prsig,
                   gid[row], row, col0, first, h);
          } else {
            load8(A0, (size_t)row*K0 + col0, 1.f, h);
          }
        }
        else if(col0 >= K0 && col0 + 8 <= K0+K1) load8(A1, (size_t)row*K1 + (col0-K0), s1, h);
        else if(col0 < K0+K1){
          float t[8];
          #pragma unroll
          for(int e=0;e<8;e++){
            int c = col0 + e; float x = 0.f;
            if(c >= K0 && c < K0+K1) x = s1 * ldA1(A1, (size_t)row*K1 + (c-K0));
            t[e] = x;
          }
          h[0]=__floats2half2_rn(t[0],t[1]); h[1]=__floats2half2_rn(t[2],t[3]);
          h[2]=__floats2half2_rn(t[4],t[5]); h[3]=__floats2half2_rn(t[6],t[7]);
        }
      }
      *(uint4*)&sA[r*FM_PH + kg*8] = *(uint4*)h;
    }
    __syncthreads();
    #pragma unroll
    for(int s=0;s<KC/16;s++){
      int ks = s*16;
      uint32_t bfr[NW1][2];
      #pragma unroll
      for(int j=0;j<NW1;j++){
        int nrow = cb1 + j*8 + lr;
        ldmB2(bfr[j], sWb + (uint32_t)(nrow*FM_PH + ks + bsel)*2);
      }
      uint32_t afr[2][4];
      #pragma unroll
      for(int mf=0;mf<2;mf++){
        int row = r0 + mf*16 + lr + ((lane>>3)&1)*8;
        ldmA4(afr[mf], sAb + (uint32_t)(row*FM_PH + ks + asel)*2);
      }
      #pragma unroll
      for(int mf=0;mf<2;mf++)
        #pragma unroll
        for(int j=0;j<NW1;j++) mma16(acc1[mf][j], afr[mf], bfr[j]);
    }
  }
  storeH(acc1, sH, r0, cb1, g, tg);

  // ---- Layer 2 (+3) ----
  float facc[2][NWF][4];
  int cbF = wc * NWF * 8;
  if constexpr (N3 == 0){
    initB(facc, b1, cbF, tg);
    gemm_smem<N1,NWF>(facc, WT1, N2, sW, sWb, sHb, tid, lane, r0, cbF);
  } else {
    constexpr int NW2 = N2/8/CW;
    int cb2 = wc * NW2 * 8;
    float acc2[2][NW2][4];
    initB(acc2, b1, cb2, tg);
    gemm_smem<N1,NW2>(acc2, WT1, N2, sW, sWb, sHb, tid, lane, r0, cb2);
    __syncthreads();
    storeH(acc2, sH, r0, cb2, g, tg);
    initB(facc, b2, cbF, tg);
    gemm_smem<N2,NWF>(facc, WT2, N3, sW, sWb, sHb, tid, lane, r0, cbF);
  }

  // ---- epilogue ----
  if constexpr (ACT == 0){
    __half* C = (__half*)Cv;
    #pragma unroll
    for(int mf=0;mf<2;mf++){
      int row0 = base + r0 + mf*16 + g;
      int row1 = row0 + 8;
      #pragma unroll
      for(int j=0;j<NWF;j++){
        int col = cbF + j*8 + 2*tg;
        if(row0 < M) *(__half2*)&C[(size_t)row0*NF + col] = __floats2half2_rn(facc[mf][j][0], facc[mf][j][1]);
        if(row1 < M) *(__half2*)&C[(size_t)row1*NF + col] = __floats2half2_rn(facc[mf][j][2], facc[mf][j][3]);
      }
    }
  } else { // ACT==2: lits epilogue
    #pragma unroll
    for(int mf=0;mf<2;mf++){
      #pragma unroll
      for(int j=0;j<NWF;j++){
        int col = cbF + j*8 + 2*tg;
        #pragma unroll
        for(int h=0;h<2;h++){
          int row = base + r0 + mf*16 + g + 8*h;
          if(row < M){
            float qa = facc[mf][j][2*h], qb = facc[mf][j][2*h+1];
            *(__half2*)&g_lits[(size_t)row*64 + col]      = __floats2half2_rn(sp(qa), sp(qb));
            *(__half2*)&g_lits[(size_t)(NV+row)*64 + col] = __floats2half2_rn(sp(-qa), sp(-qb));
            *(__half2*)&g_sig [(size_t)row*64 + col]      =
                __floats2half2_rn(1.f/(1.f+expf(-qa)), 1.f/(1.f+expf(-qb)));
          }
        }
      }
    }
  }

  // ---- fused group stats on final output cols [NF-64, NF) ----
  if constexpr (STATS){
    int glast = min(base+127, M-1);
    int g0 = gid[base];
    bool fast = (g0 == gid[glast]);
    #pragma unroll
    for(int j=0;j<NWF;j++){
      int col = cbF + j*8 + 2*tg;
      if(col >= NF-64){
        int sc = col - (NF-64);
        float s0=0.f,q0=0.f,s1=0.f,q1=0.f;
        #pragma unroll
        for(int mf=0;mf<2;mf++){
          #pragma unroll
          for(int h=0;h<2;h++){
            int row = base + r0 + mf*16 + g + 8*h;
            if(row < M){
              float v0=facc[mf][j][2*h], v1=facc[mf][j][2*h+1];
              if(fast){ s0+=v0; q0+=v0*v0; s1+=v1; q1+=v1*v1; }
              else {
                int gr = gid[row];
                atomicAdd(&statbuf[gr*64+sc], v0);
                atomicAdd(&statbuf[NG*64+gr*64+sc], v0*v0);
                atomicAdd(&statbuf[gr*64+sc+1], v1);
                atomicAdd(&statbuf[NG*64+gr*64+sc+1], v1*v1);
              }
            }
          }
        }
        if(fast){
          #pragma unroll
          for(int o=16;o>=4;o>>=1){
            s0+=__shfl_down_sync(0xffffffffu,s0,o);
            q0+=__shfl_down_sync(0xffffffffu,q0,o);
            s1+=__shfl_down_sync(0xffffffffu,s1,o);
            q1+=__shfl_down_sync(0xffffffffu,q1,o);
          }
          if(lane < 4){
            atomicAdd(&statbuf[g0*64+sc], s0);
            atomicAdd(&statbuf[NG*64+g0*64+sc], q0);
            atomicAdd(&statbuf[g0*64+sc+1], s1);
            atomicAdd(&statbuf[NG*64+g0*64+sc+1], q1);
          }
        }
      }
    }
  }
}

// ----------------- head (fused final clause apply, read-only) ---------------
__global__ void __launch_bounds__(256) k_head(
    const int* __restrict__ cg, const __half* __restrict__ WT,
    const float* __restrict__ b, float* __restrict__ C, int M,
    const float* __restrict__ w2, const float* __restrict__ b2){
  constexpr int KC = 64, PH = 72, N = 64, NW = 8;
  __shared__ __align__(16) __half sA[128*PH];
  __shared__ __align__(16) __half sW[N*PH];
  int tid = threadIdx.x;
  int w = tid >> 5, lane = tid & 31;
  int g = lane >> 2, tg = lane & 3;
  int base = blockIdx.x * 128;
  int r0 = w * 16;
  float acc[NW][4];
  #pragma unroll
  for(int j=0;j<NW;j++){
    int col = j*8 + 2*tg;
    float b0v = b[col], b1v = b[col+1];
    acc[j][0]=b0v; acc[j][1]=b1v; acc[j][2]=b0v; acc[j][3]=b1v;
  }
  uint32_t sAb = (uint32_t)__cvta_generic_to_shared(sA);
  uint32_t sWb = (uint32_t)__cvta_generic_to_shared(sW);
  for(int i=tid; i<N*(KC/8); i+=256){
    int n = i/(KC/8), kg = i%(KC/8);
    *(uint4*)&sW[n*PH + kg*8] = *(const uint4*)&WT[(size_t)n*64 + kg*8];
  }
  for(int i=tid; i<128*(KC/8); i+=256){
    int r = i/(KC/8), kg = i%(KC/8);
    int row = base + r;
    int col0 = kg*8;
    __half2 h[4];
    h[0]=h[1]=h[2]=h[3]=__float2half2_rn(0.f);
    if(row < M){
      int gg = cg[row];
      uint4 pu = *(const uint4*)&g_cd[(size_t)row*128 + 64 + col0];
      __half2* ph = (__half2*)&pu;
      const float* mb = &g_meanC[gg*64 + col0];
      const float* rb = &g_rsigC[gg*64 + col0];
      const float* sb = &g_clauses[(size_t)row*64 + col0];
      float4 m0=*(const float4*)mb, m1=*(const float4*)(mb+4);
      float4 rr0=*(const float4*)rb, rr1=*(const float4*)(rb+4);
      float4 s0=*(const float4*)sb, s1=*(const float4*)(sb+4);
      float2 p0=__half22float2(ph[0]), p1=__half22float2(ph[1]);
      float2 p2=__half22float2(ph[2]), p3=__half22float2(ph[3]);
      float nv0=(p0.x-m0.x)*rr0.x*0.25f + 0.1f*s0.x;
      float nv1=(p0.y-m0.y)*rr0.y*0.25f + 0.1f*s0.y;
      float nv2=(p1.x-m0.z)*rr0.z*0.25f + 0.1f*s0.z;
      float nv3=(p1.y-m0.w)*rr0.w*0.25f + 0.1f*s0.w;
      float nv4=(p2.x-m1.x)*rr1.x*0.25f + 0.1f*s1.x;
      float nv5=(p2.y-m1.y)*rr1.y*0.25f + 0.1f*s1.y;
      float nv6=(p3.x-m1.z)*rr1.z*0.25f + 0.1f*s1.z;
      float nv7=(p3.y-m1.w)*rr1.w*0.25f + 0.1f*s1.w;
      h[0]=__floats2half2_rn(nv0,nv1); h[1]=__floats2half2_rn(nv2,nv3);
      h[2]=__floats2half2_rn(nv4,nv5); h[3]=__floats2half2_rn(nv6,nv7);
    }
    *(uint4*)&sA[r*PH + col0] = *(uint4*)h;
  }
  __syncthreads();
  int lr = lane & 7;
  #pragma unroll
  for(int s=0;s<KC/16;s++){
    int ks = s*16;
    uint32_t bfr[NW][2];
    #pragma unroll
    for(int j=0;j<NW;j++){
      int nrow = j*8 + lr;
      ldmB2(bfr[j], sWb + (uint32_t)(nrow*PH + ks + ((lane>>3)&1)*8)*2);
    }
    uint32_t afr[4];
    {
      int row = r0 + lr + ((lane>>3)&1)*8;
      ldmA4(afr, sAb + (uint32_t)(row*PH + ks + ((lane>>4)&1)*8)*2);
    }
    #pragma unroll
    for(int j=0;j<NW;j++) mma16(acc[j], afr, bfr[j]);
  }
  float p0 = 0.f, p1 = 0.f;
  #pragma unroll
  for(int j=0;j<NW;j++){
    int col = j*8 + 2*tg;
    float wa = w2[col], wb = w2[col+1];
    p0 += lrelu(acc[j][0])*wa + lrelu(acc[j][1])*wb;
    p1 += lrelu(acc[j][2])*wa + lrelu(acc[j][3])*wb;
  }
  #pragma unroll
  for(int o=2;o>0;o>>=1){
    p0 += __shfl_down_sync(0xffffffffu, p0, o, 4);
    p1 += __shfl_down_sync(0xffffffffu, p1, o, 4);
  }
  if(tg == 0){
    int row0 = base + r0 + g;
    int row1 = row0 + 8;
    float bb = b2[0];
    if(row0 < M){
      float lg = p0 + bb;
      C[row0] = 1.f/(1.f+expf(-lg)); C[NC + row0] = sp(lg);
    }
    if(row1 < M){
      float lg = p1 + bb;
      C[row1] = 1.f/(1.f+expf(-lg)); C[NC + row1] = sp(lg);
    }
  }
  // zero gcnt for next graph replay
  if(blockIdx.x == 0 && tid < 2*NG) g_gcnt[tid] = 0;
}

// ----------------- per-round graph kernels -----------------
__global__ void k_cl(const int* __restrict__ lit){
  int idx = blockIdx.x*blockDim.x + threadIdx.x;
  if(idx >= NC*8) return;
  int c = idx >> 3, q = (idx & 7) * 8;
  int e = 3*c;
  int l0 = lit[e], l1 = lit[e+1], l2 = lit[e+2];
  uint4 ua = *(const uint4*)&g_lits[(size_t)l0*64 + q];
  uint4 ub = *(const uint4*)&g_lits[(size_t)l1*64 + q];
  uint4 uc = *(const uint4*)&g_lits[(size_t)l2*64 + q];
  __half2* pa = (__half2*)&ua; __half2* pb = (__half2*)&ub; __half2* pc = (__half2*)&uc;
  __half2 o[4];
  #pragma unroll
  for(int p=0;p<4;p++){
    float2 fa = __half22float2(pa[p]), fb = __half22float2(pb[p]), fc = __half22float2(pc[p]);
    o[p] = __floats2half2_rn(expf(-(fa.x+fb.x+fc.x)), expf(-(fa.y+fb.y+fc.y)));
  }
  *(uint4*)&g_cl[(size_t)c*64 + q] = *(uint4*)o;
}

__global__ void __launch_bounds__(256) k_uin(){
  int tid = threadIdx.x;
  int f = tid & 63;
  int v = blockIdx.x*4 + (tid >> 6);
  if(v >= NV) return;
  int p0 = g_off[v],    p1 = g_off[v+1];
  int n0 = g_off[NV+v], n1 = g_off[NV+v+1];
  float scl=0.f, scd=0.f, ncl=0.f, ncd=0.f;
  for(int e=p0;e<p1;e++){
    int c = g_pcl[e];
    scl += __half2float(g_cl[(size_t)c*64 + f]);
    scd += __half2float(g_cd[(size_t)c*128 + f]);
  }
  for(int e=n0;e<n1;e++){
    int c = g_pcl[e];
    ncl += __half2float(g_cl[(size_t)c*64 + f]);
    ncd += __half2float(g_cd[(size_t)c*128 + f]);
  }
  float sg = __half2float(g_sig[(size_t)v*64 + f]);
  float gr = (-sg*scl + (1.f-sg)*ncl) * g_vdw[v];
  size_t o = (size_t)v*256;
  g_uin[o + f]       = __float2half_rn(gr);
  g_uin[o + 64 + f]  = __float2half_rn(g_vars[(size_t)v*64 + f]);
  g_uin[o + 128 + f] = __float2half_rn(scd * g_dw[v]);
  g_uin[o + 192 + f] = __float2half_rn(ncd * g_dw[NV+v]);
}

// mean/rsig for BOTH C and V stats; self-clears stat buffers
__global__ void k_fin2(){
  int i = blockIdx.x*blockDim.x + threadIdx.x;
  if(i >= 2*NG*64) return;
  bool isV = (i >= NG*64);
  int ii = isV ? i - NG*64 : i;
  int gg = ii >> 6;
  float* stat = isV ? g_statV : g_statC;
  float cnt = (float)g_gcnt[(isV ? NG : 0) + gg];
  float inv = 1.f / fmaxf(cnt, 1.f);
  float m = stat[ii] * inv;
  float var = stat[NG*64 + ii] * inv - m*m;
  if(isV){ g_meanV[ii]=m; g_rsigV[ii]=rsqrtf(fmaxf(var,0.f)+1e-6f); }
  else   { g_meanC[ii]=m; g_rsigC[ii]=rsqrtf(fmaxf(var,0.f)+1e-6f); }
  stat[ii]=0.f; stat[NG*64+ii]=0.f;
}

// ----------------- host -----------------
static void* sym(const void* s){ void* p=nullptr; cudaGetSymbolAddress(&p, s); return p; }

extern "C" void kernel_launch(void* const* d_in, const int* in_sizes, int n_in,
                              void* d_out, int out_size){
  const int*   lit   = (const int*)d_in[0];
  const int*   vg    = (const int*)d_in[2];
  const int*   cg    = (const int*)d_in[3];
  const float* noise = (const float*)d_in[4];
  const float *qW0=(const float*)d_in[5],  *qb0=(const float*)d_in[6];
  const float *qW1=(const float*)d_in[7],  *qb1=(const float*)d_in[8];
  const float *cW0=(const float*)d_in[9],  *cb0=(const float*)d_in[10];
  const float *cW1=(const float*)d_in[11], *cb1=(const float*)d_in[12];
  const float *uW0=(const float*)d_in[13], *ub0=(const float*)d_in[14];
  const float *uW1=(const float*)d_in[15], *ub1=(const float*)d_in[16];
  const float *uW2=(const float*)d_in[17], *ub2=(const float*)d_in[18];
  const float *oW0=(const float*)d_in[19], *ob0=(const float*)d_in[20];
  const float *oW1=(const float*)d_in[21], *ob1=(const float*)d_in[22];
  float* out = (float*)d_out;

  float  *p_vars  = (float*)sym(g_vars),   *p_claus = (float*)sym(g_clauses);
  float  *p_statC = (float*)sym(g_statC),  *p_statV = (float*)sym(g_statV);
  float  *p_meanC = (float*)sym(g_meanC),  *p_rsigC = (float*)sym(g_rsigC);
  float  *p_meanV = (float*)sym(g_meanV),  *p_rsigV = (float*)sym(g_rsigV);
  __half *p_cd = (__half*)sym(g_cd), *p_cl = (__half*)sym(g_cl);
  __half *p_uin = (__half*)sym(g_uin), *p_vraw = (__half*)sym(g_vraw);
  __half *t_q0 = (__half*)sym(g_qW0h), *t_q1 = (__half*)sym(g_qW1h);
  __half *t_c0 = (__half*)sym(g_cW0h), *t_c1 = (__half*)sym(g_cW1h);
  __half *t_u0 = (__half*)sym(g_uW0h), *t_u1 = (__half*)sym(g_uW1h), *t_u2 = (__half*)sym(g_uW2h);
  __half *t_o0 = (__half*)sym(g_oW0h);
  const __half* hnull = nullptr;

  auto fq = k_fmlp<float,float,64,4,64,64,0,2,1,0>;
  auto fc = k_fmlp<float,__half,64,64,128,128,0,0,1,1>;
  auto fu = k_fmlp<__half,__half,256,0,128,128,64,0,0,1>;
  cudaFuncSetAttribute(fq, cudaFuncAttributeMaxDynamicSharedMemorySize, FM_SMEM);
  cudaFuncSetAttribute(fc, cudaFuncAttributeMaxDynamicSharedMemorySize, FM_SMEM);
  cudaFuncSetAttribute(fu, cudaFuncAttributeMaxDynamicSharedMemorySize, FM_SMEM);

  const int T = 256;
  auto B = [](long n){ return (int)((n + 255) / 256); };
  int mbV = (NV + 127) / 128, mbC = (NC + 127) / 128;

  k_count<<<1024, T>>>(lit, vg, cg);
  k_scan<<<1, 1024>>>();
  k_fillw<<<256, T>>>(lit, qW0, qW1, cW0, cW1, uW0, uW1, uW2, oW0);

  for(int t = 0; t < ROUNDS; t++){
    const float* nz = noise + (size_t)t * NV * 4;
    int first = (t == 0) ? 1 : 0;
    // query MLP: fused vars pair-norm apply + lits epilogue
    fq<<<mbV, T, FM_SMEM>>>(p_vars, nz, 1.f, p_vraw, 64, 0, p_meanV, p_rsigV, vg, first,
                            t_q0, qb0, t_q1, qb1, hnull, nullptr, nullptr, NV, nullptr);
    k_cl<<<B((long)NC*8), T>>>(lit);
    // clause MLP: fused clauses apply + output stats
    fc<<<mbC, T, FM_SMEM>>>(p_claus, p_cl, 4.f, p_cd, 128, 64, p_meanC, p_rsigC, cg, first,
                            t_c0, cb0, t_c1, cb1, hnull, nullptr, p_cd, NC, p_statC);
    k_uin<<<(NV+3)/4, T>>>();
    // update MLP: stats on vraw
    fu<<<mbV, T, FM_SMEM>>>(p_uin, hnull, 0.f, hnull, 0, 0, nullptr, nullptr, vg, 0,
                            t_u0, ub0, t_u1, ub1, t_u2, ub2, p_vraw, NV, p_statV);
    k_fin2<<<B(2L*NG*64), T>>>();
  }

  k_head<<<mbC, T>>>(cg, t_o0, ob0, out, NC, oW1, ob1);

  (void)in_sizes; (void)n_in; (void)out_size;
}